// round 1
// baseline (speedup 1.0000x reference)
#include <cuda_runtime.h>
#include <math.h>

// ---------------------------------------------------------------------------
// Problem constants
// ---------------------------------------------------------------------------
#define NL 2
#define HH 4
#define CC 512
#define INDIM 256
#define FAN 16
#define BSEED 256
#define NC 47
#define DH 128
#define N0 256
#define N1 4096
#define N2 65536

// ---------------------------------------------------------------------------
// Device scratch (static globals -- the sanctioned allocation-free scratch)
// ---------------------------------------------------------------------------
__device__ float g_S1E[N1 * CC];        // depth-1 embedded state (pre-layer)
__device__ float g_S1N[N1 * CC];        // depth-1 state after layer 0
__device__ float g_S0[N0 * CC];         // depth-0 state (reused across layers)
__device__ float g_AGGF[N1 * INDIM];    // aggregated raw feats2
__device__ float g_AGGC[N1];            // per-row bias coefficient
__device__ float g_AGG[N1 * CC];        // aggregated state input to sage
__device__ float g_CAT[N1 * 2 * CC];    // concat(sf, agg)
__device__ float g_HL[N1 * CC];         // sage local output
__device__ float g_H1[N1 * CC];         // after LN1
__device__ float g_QKV[N1 * 3 * CC];    // qkv projection
__device__ float g_SC[(long long)HH * N1 * N1];  // attention scores (256 MB)
__device__ float g_ATTO[N1 * CC];       // per-head attention output, concat layout
__device__ float g_ATT[N1 * CC];        // after output projection
__device__ float g_H2[N1 * CC];         // after LN2
__device__ float g_FF1[N1 * 2 * CC];    // FFN hidden

// ---------------------------------------------------------------------------
// Generic tiled SGEMM:  C = alpha * A x op(B) + epilogue
//   A: [M,K] row-major (lda), op(B): transB ? B[N,K] : B[K,N]
//   epilogue: + bias[n]*biasScale[m], relu, + addC, * rowMask[m]
//   batched over blockIdx.z with element strides sA/sB/sC
// ---------------------------------------------------------------------------
#define BM 64
#define BN 64
#define BK 16

__global__ void gemm_kernel(
    int M, int N, int K,
    const float* __restrict__ A, int lda, long long sA,
    const float* __restrict__ B, int ldb, long long sB, int transB,
    float* __restrict__ C, int ldc, long long sC,
    float alpha,
    const float* __restrict__ bias,
    const float* __restrict__ biasScale,
    int relu,
    const float* __restrict__ addC,
    const float* __restrict__ rowMask)
{
    __shared__ __align__(16) float As[BK][BM];
    __shared__ __align__(16) float Bs[BK][BN];

    int bz = blockIdx.z;
    A += (long long)bz * sA;
    B += (long long)bz * sB;
    C += (long long)bz * sC;

    int bm = blockIdx.y * BM;
    int bn = blockIdx.x * BN;
    int tid = threadIdx.x;
    int tx = tid & 15;
    int ty = tid >> 4;

    float acc[4][4] = {};

    for (int k0 = 0; k0 < K; k0 += BK) {
        // load A tile (64x16) as As[k][m]
        #pragma unroll
        for (int i = 0; i < 4; i++) {
            int li = tid + i * 256;
            int k = li & 15, m = li >> 4;
            int gm = bm + m;
            As[k][m] = (gm < M) ? A[(long long)gm * lda + (k0 + k)] : 0.0f;
        }
        if (transB) {
            #pragma unroll
            for (int i = 0; i < 4; i++) {
                int li = tid + i * 256;
                int k = li & 15, n = li >> 4;
                int gn = bn + n;
                Bs[k][n] = (gn < N) ? B[(long long)gn * ldb + (k0 + k)] : 0.0f;
            }
        } else {
            #pragma unroll
            for (int i = 0; i < 4; i++) {
                int li = tid + i * 256;
                int n = li & 63, k = li >> 6;
                int gn = bn + n;
                Bs[k][n] = (gn < N) ? B[(long long)(k0 + k) * ldb + gn] : 0.0f;
            }
        }
        __syncthreads();
        #pragma unroll
        for (int kk = 0; kk < BK; kk++) {
            float4 a4 = reinterpret_cast<float4*>(As[kk])[ty];
            float4 b4 = reinterpret_cast<float4*>(Bs[kk])[tx];
            float ra[4] = {a4.x, a4.y, a4.z, a4.w};
            float rb[4] = {b4.x, b4.y, b4.z, b4.w};
            #pragma unroll
            for (int i = 0; i < 4; i++)
                #pragma unroll
                for (int j = 0; j < 4; j++)
                    acc[i][j] = fmaf(ra[i], rb[j], acc[i][j]);
        }
        __syncthreads();
    }

    #pragma unroll
    for (int i = 0; i < 4; i++) {
        int gm = bm + ty * 4 + i;
        if (gm >= M) continue;
        float bs = biasScale ? biasScale[gm] : 1.0f;
        float rm = rowMask ? rowMask[gm] : 1.0f;
        #pragma unroll
        for (int j = 0; j < 4; j++) {
            int gn = bn + tx * 4 + j;
            if (gn >= N) continue;
            float v = acc[i][j] * alpha;
            if (bias) v += bias[gn] * bs;
            if (relu) v = fmaxf(v, 0.0f);
            if (addC) v += addC[(long long)gm * ldc + gn];
            v *= rm;
            C[(long long)gm * ldc + gn] = v;
        }
    }
}

// ---------------------------------------------------------------------------
// Block reductions (256-thread blocks, 8 warps)
// ---------------------------------------------------------------------------
__device__ __forceinline__ float blockReduceSum(float v, float* red) {
    #pragma unroll
    for (int o = 16; o > 0; o >>= 1) v += __shfl_xor_sync(0xffffffffu, v, o);
    int w = threadIdx.x >> 5;
    if ((threadIdx.x & 31) == 0) red[w] = v;
    __syncthreads();
    float r;
    if (threadIdx.x < 32) {
        r = (threadIdx.x < (blockDim.x >> 5)) ? red[threadIdx.x] : 0.0f;
        #pragma unroll
        for (int o = 16; o > 0; o >>= 1) r += __shfl_xor_sync(0xffffffffu, r, o);
        if (threadIdx.x == 0) red[0] = r;
    }
    __syncthreads();
    r = red[0];
    __syncthreads();
    return r;
}

__device__ __forceinline__ float blockReduceMax(float v, float* red) {
    #pragma unroll
    for (int o = 16; o > 0; o >>= 1) v = fmaxf(v, __shfl_xor_sync(0xffffffffu, v, o));
    int w = threadIdx.x >> 5;
    if ((threadIdx.x & 31) == 0) red[w] = v;
    __syncthreads();
    float r;
    if (threadIdx.x < 32) {
        r = (threadIdx.x < (blockDim.x >> 5)) ? red[threadIdx.x] : -1e30f;
        #pragma unroll
        for (int o = 16; o > 0; o >>= 1) r = fmaxf(r, __shfl_xor_sync(0xffffffffu, r, o));
        if (threadIdx.x == 0) red[0] = r;
    }
    __syncthreads();
    r = red[0];
    __syncthreads();
    return r;
}

// ---------------------------------------------------------------------------
// Row softmax, in place. grid = (rows, batch), 256 threads. N <= 4096.
// ---------------------------------------------------------------------------
__global__ void softmax_kernel(float* __restrict__ S, int N, int ld, long long bStride)
{
    float* row = S + (long long)blockIdx.y * bStride + (long long)blockIdx.x * ld;
    int tid = threadIdx.x;
    int nIter = (N + 255) >> 8;
    float v[16];
    float mx = -1e30f;
    for (int i = 0; i < nIter; i++) {
        int idx = tid + (i << 8);
        v[i] = (idx < N) ? row[idx] : -1e30f;
        mx = fmaxf(mx, v[i]);
    }
    __shared__ float red[8];
    mx = blockReduceMax(mx, red);
    float s = 0.0f;
    for (int i = 0; i < nIter; i++) {
        v[i] = __expf(v[i] - mx);
        int idx = tid + (i << 8);
        if (idx >= N) v[i] = 0.0f;
        s += v[i];
    }
    s = blockReduceSum(s, red);
    float inv = 1.0f / s;
    for (int i = 0; i < nIter; i++) {
        int idx = tid + (i << 8);
        if (idx < N) row[idx] = v[i] * inv;
    }
}

// ---------------------------------------------------------------------------
// out[row] = LN(a[row] + b[row]) * g + beta,  C = 512, 256 threads/block
// ---------------------------------------------------------------------------
__global__ void add_ln_kernel(const float* __restrict__ a, const float* __restrict__ b,
                              const float* __restrict__ g, const float* __restrict__ be,
                              float* __restrict__ out)
{
    long long row = blockIdx.x;
    const float* ar = a + row * CC;
    const float* br = b + row * CC;
    int tid = threadIdx.x;
    float x0 = ar[tid] + br[tid];
    float x1 = ar[tid + 256] + br[tid + 256];
    __shared__ float red[8];
    float mu = blockReduceSum(x0 + x1, red) * (1.0f / CC);
    float d0 = x0 - mu, d1 = x1 - mu;
    float var = blockReduceSum(d0 * d0 + d1 * d1, red) * (1.0f / CC);
    float rstd = rsqrtf(var + 1e-5f);
    out[row * CC + tid]       = d0 * rstd * g[tid] + be[tid];
    out[row * CC + tid + 256] = d1 * rstd * g[tid + 256] + be[tid + 256];
}

// ---------------------------------------------------------------------------
// Masked-mean neighbor aggregation:
//  out[p,c] = sum_f (nbm[p,f]*childMask?) * X[p*16+f, c] / clip(sum_f nbm, 1)
//  coefOut[p] = sum_f w / denom  (for folding embedding bias through agg)
// ---------------------------------------------------------------------------
__global__ void agg_kernel(const float* __restrict__ X, int C,
                           const int* __restrict__ nbm,
                           const float* __restrict__ childMask,
                           float* __restrict__ out, float* __restrict__ coefOut, int P)
{
    long long idx = (long long)blockIdx.x * blockDim.x + threadIdx.x;
    if (idx >= (long long)P * C) return;
    int p = (int)(idx / C);
    int c = (int)(idx % C);
    float sum = 0.0f, den = 0.0f, wsum = 0.0f;
    #pragma unroll
    for (int f = 0; f < FAN; f++) {
        float nb = (float)nbm[p * FAN + f];
        den += nb;
        float w = nb * (childMask ? childMask[p * FAN + f] : 1.0f);
        wsum += w;
        sum += w * X[(long long)(p * FAN + f) * C + c];
    }
    den = fmaxf(den, 1.0f);
    out[(long long)p * C + c] = sum / den;
    if (coefOut && c == 0) coefOut[p] = wsum / den;
}

// ---------------------------------------------------------------------------
// out[m, 0:512] = a[m], out[m, 512:1024] = b[m]
// ---------------------------------------------------------------------------
__global__ void concat_kernel(const float* __restrict__ a, const float* __restrict__ b,
                              float* __restrict__ out, int n)
{
    long long idx = (long long)blockIdx.x * blockDim.x + threadIdx.x;
    if (idx >= (long long)n * 2 * CC) return;
    int m = (int)(idx >> 10);
    int c = (int)(idx & 1023);
    out[idx] = (c < CC) ? a[(long long)m * CC + c] : b[(long long)m * CC + c - CC];
}

// ---------------------------------------------------------------------------
// Host-side orchestration
// ---------------------------------------------------------------------------
static void gemm(int M, int N, int K,
                 const float* A, int lda, long long sA,
                 const float* B, int ldb, long long sB, int transB,
                 float* C, int ldc, long long sC, int nbatch,
                 float alpha, const float* bias, const float* biasScale, int relu,
                 const float* addC, const float* rowMask)
{
    dim3 grid((N + BN - 1) / BN, (M + BM - 1) / BM, nbatch);
    gemm_kernel<<<grid, 256>>>(M, N, K, A, lda, sA, B, ldb, sB, transB,
                               C, ldc, sC, alpha, bias, biasScale, relu, addC, rowMask);
}

struct Scratch {
    float *S1E, *S1N, *S0, *AGGF, *AGGC, *AGG, *CAT, *HL, *H1, *QKV, *SC, *ATTO, *ATT, *H2, *FF1;
};

static Scratch get_scratch() {
    Scratch s;
    void* p;
    cudaGetSymbolAddress(&p, g_S1E);  s.S1E  = (float*)p;
    cudaGetSymbolAddress(&p, g_S1N);  s.S1N  = (float*)p;
    cudaGetSymbolAddress(&p, g_S0);   s.S0   = (float*)p;
    cudaGetSymbolAddress(&p, g_AGGF); s.AGGF = (float*)p;
    cudaGetSymbolAddress(&p, g_AGGC); s.AGGC = (float*)p;
    cudaGetSymbolAddress(&p, g_AGG);  s.AGG  = (float*)p;
    cudaGetSymbolAddress(&p, g_CAT);  s.CAT  = (float*)p;
    cudaGetSymbolAddress(&p, g_HL);   s.HL   = (float*)p;
    cudaGetSymbolAddress(&p, g_H1);   s.H1   = (float*)p;
    cudaGetSymbolAddress(&p, g_QKV);  s.QKV  = (float*)p;
    cudaGetSymbolAddress(&p, g_SC);   s.SC   = (float*)p;
    cudaGetSymbolAddress(&p, g_ATTO); s.ATTO = (float*)p;
    cudaGetSymbolAddress(&p, g_ATT);  s.ATT  = (float*)p;
    cudaGetSymbolAddress(&p, g_H2);   s.H2   = (float*)p;
    cudaGetSymbolAddress(&p, g_FF1);  s.FF1  = (float*)p;
    return s;
}

struct LayerW {
    const float *sageW, *sageB, *qkvW, *qkvB, *outW, *outB;
    const float *n1g, *n1b, *n2g, *n2b, *ffnW1, *ffnB1, *ffnW2, *ffnB2;
};

// one transformer block for n nodes: sf = current state, agg = aggregated neighbor state
static void block_forward(int n, const float* sf, const float* agg, float* outState,
                          const float* rowMask, const LayerW& w, const Scratch& s)
{
    const float scale = 0.08838834764831845f;  // 1/sqrt(128)

    // concat + GraphSAGE update
    concat_kernel<<<(int)(((long long)n * 2 * CC + 255) / 256), 256>>>(sf, agg, s.CAT, n);
    gemm(n, CC, 2 * CC, s.CAT, 2 * CC, 0, w.sageW, 2 * CC, 0, 1,
         s.HL, CC, 0, 1, 1.0f, w.sageB, nullptr, 0, nullptr, nullptr);
    add_ln_kernel<<<n, 256>>>(sf, s.HL, w.n1g, w.n1b, s.H1);

    // MHA
    gemm(n, 3 * CC, CC, s.H1, CC, 0, w.qkvW, CC, 0, 1,
         s.QKV, 3 * CC, 0, 1, 1.0f, w.qkvB, nullptr, 0, nullptr, nullptr);
    // scores per head: S = Q @ K^T * scale
    gemm(n, n, DH, s.QKV, 3 * CC, DH, s.QKV + CC, 3 * CC, DH, 1,
         s.SC, n, (long long)n * n, HH, scale, nullptr, nullptr, 0, nullptr, nullptr);
    {
        dim3 grid(n, HH);
        softmax_kernel<<<grid, 256>>>(s.SC, n, n, (long long)n * n);
    }
    // O_h = S @ V_h
    gemm(n, DH, n, s.SC, n, (long long)n * n, s.QKV + 2 * CC, 3 * CC, DH, 0,
         s.ATTO, CC, DH, HH, 1.0f, nullptr, nullptr, 0, nullptr, nullptr);
    // output projection
    gemm(n, CC, CC, s.ATTO, CC, 0, w.outW, CC, 0, 1,
         s.ATT, CC, 0, 1, 1.0f, w.outB, nullptr, 0, nullptr, nullptr);
    add_ln_kernel<<<n, 256>>>(s.H1, s.ATT, w.n2g, w.n2b, s.H2);

    // FFN with fused residual + node-mask in the second GEMM epilogue
    gemm(n, 2 * CC, CC, s.H2, CC, 0, w.ffnW1, CC, 0, 1,
         s.FF1, 2 * CC, 0, 1, 1.0f, w.ffnB1, nullptr, 1, nullptr, nullptr);
    gemm(n, CC, 2 * CC, s.FF1, 2 * CC, 0, w.ffnW2, 2 * CC, 0, 1,
         outState, CC, 0, 1, 1.0f, w.ffnB2, nullptr, 0, s.H2, rowMask);
}

extern "C" void kernel_launch(void* const* d_in, const int* in_sizes, int n_in,
                              void* d_out, int out_size)
{
    const float* feats0  = (const float*)d_in[0];
    const float* feats1  = (const float*)d_in[1];
    const float* feats2  = (const float*)d_in[2];
    const float* nmask0  = (const float*)d_in[3];
    const float* nmask1  = (const float*)d_in[4];
    const float* nmask2  = (const float*)d_in[5];
    const int*   nbmask0 = (const int*)d_in[6];
    const int*   nbmask1 = (const int*)d_in[7];
    const float* emb_w   = (const float*)d_in[8];
    const float* emb_b   = (const float*)d_in[9];
    const float* sage_w  = (const float*)d_in[10];
    const float* sage_b  = (const float*)d_in[11];
    const float* qkv_w   = (const float*)d_in[12];
    const float* qkv_b   = (const float*)d_in[13];
    const float* out_w   = (const float*)d_in[14];
    const float* out_b   = (const float*)d_in[15];
    const float* n1_g    = (const float*)d_in[16];
    const float* n1_b    = (const float*)d_in[17];
    const float* n2_g    = (const float*)d_in[18];
    const float* n2_b    = (const float*)d_in[19];
    const float* ffn_w1  = (const float*)d_in[20];
    const float* ffn_b1  = (const float*)d_in[21];
    const float* ffn_w2  = (const float*)d_in[22];
    const float* ffn_b2  = (const float*)d_in[23];
    const float* cls_w   = (const float*)d_in[24];
    const float* cls_b   = (const float*)d_in[25];
    float* out = (float*)d_out;

    Scratch s = get_scratch();

    LayerW w[NL];
    for (int li = 0; li < NL; li++) {
        w[li].sageW = sage_w + (long long)li * CC * 2 * CC;
        w[li].sageB = sage_b + li * CC;
        w[li].qkvW  = qkv_w  + (long long)li * 3 * CC * CC;
        w[li].qkvB  = qkv_b  + li * 3 * CC;
        w[li].outW  = out_w  + (long long)li * CC * CC;
        w[li].outB  = out_b  + li * CC;
        w[li].n1g   = n1_g + li * CC;  w[li].n1b = n1_b + li * CC;
        w[li].n2g   = n2_g + li * CC;  w[li].n2b = n2_b + li * CC;
        w[li].ffnW1 = ffn_w1 + (long long)li * 2 * CC * CC;
        w[li].ffnB1 = ffn_b1 + li * 2 * CC;
        w[li].ffnW2 = ffn_w2 + (long long)li * CC * 2 * CC;
        w[li].ffnB2 = ffn_b2 + li * CC;
    }

    // ---- embeddings (depth 0 and 1), masked ----
    gemm(N0, CC, INDIM, feats0, INDIM, 0, emb_w, INDIM, 0, 1,
         s.S0, CC, 0, 1, 1.0f, emb_b, nullptr, 0, nullptr, nmask0);
    gemm(N1, CC, INDIM, feats1, INDIM, 0, emb_w, INDIM, 0, 1,
         s.S1E, CC, 0, 1, 1.0f, emb_b, nullptr, 0, nullptr, nmask1);

    // ---- depth-2: aggregate RAW features first (embedding commutes with linear agg) ----
    agg_kernel<<<(int)(((long long)N1 * INDIM + 255) / 256), 256>>>(
        feats2, INDIM, nbmask1, nmask2, s.AGGF, s.AGGC, N1);
    // agg state for depth-1 sage: AGGF @ emb_w.T + coef * emb_b
    gemm(N1, CC, INDIM, s.AGGF, INDIM, 0, emb_w, INDIM, 0, 1,
         s.AGG, CC, 0, 1, 1.0f, emb_b, s.AGGC, 0, nullptr, nullptr);

    // ---- layer 0, depth 1 (n = 4096) ----
    block_forward(N1, s.S1E, s.AGG, s.S1N, nmask1, w[0], s);

    // ---- layer 0, depth 0 (n = 256): neighbors from PRE-layer depth-1 states ----
    agg_kernel<<<(int)(((long long)N0 * CC + 255) / 256), 256>>>(
        s.S1E, CC, nbmask0, nullptr, s.AGG, nullptr, N0);
    block_forward(N0, s.S0, s.AGG, s.S0, nmask0, w[0], s);

    // ---- layer 1, depth 0 (n = 256): neighbors from post-layer-0 depth-1 states ----
    agg_kernel<<<(int)(((long long)N0 * CC + 255) / 256), 256>>>(
        s.S1N, CC, nbmask0, nullptr, s.AGG, nullptr, N0);
    block_forward(N0, s.S0, s.AGG, s.S0, nmask0, w[1], s);

    // ---- classifier ----
    gemm(N0, NC, CC, s.S0, CC, 0, cls_w, CC, 0, 1,
         out, NC, 0, 1, 1.0f, cls_b, nullptr, 0, nullptr, nullptr);
}

// round 2
// speedup vs baseline: 2.2492x; 2.2492x over previous
#include <cuda_runtime.h>
#include <math.h>
#include <stdint.h>

// ---------------------------------------------------------------------------
// Problem constants
// ---------------------------------------------------------------------------
#define NL 2
#define HH 4
#define CC 512
#define INDIM 256
#define FAN 16
#define NC 47
#define DH 128
#define N0 256
#define N1 4096
#define N2 65536

// ---------------------------------------------------------------------------
// Device scratch
// ---------------------------------------------------------------------------
__device__ float g_S1E[N1 * CC];
__device__ float g_S1N[N1 * CC];
__device__ float g_S0[N0 * CC];
__device__ float g_AGGF[N1 * INDIM];
__device__ float g_AGGC[N1];
__device__ float g_AGG[N1 * CC];
__device__ float g_CAT[N1 * 2 * CC];
__device__ float g_HL[N1 * CC];
__device__ float g_H1[N1 * CC];
__device__ float g_QKV[N1 * 3 * CC];
__device__ float g_SC[(long long)HH * N1 * N1];
__device__ float g_ATTO[N1 * CC];
__device__ float g_ATT[N1 * CC];
__device__ float g_H2[N1 * CC];
__device__ float g_FF1[N1 * 2 * CC];

// ---------------------------------------------------------------------------
// tf32 helpers
// ---------------------------------------------------------------------------
__device__ __forceinline__ uint32_t f2tf32(float f) {
    uint32_t u;
    asm("cvt.rna.tf32.f32 %0, %1;" : "=r"(u) : "f"(f));
    return u;
}

__device__ __forceinline__ void mma_tf32(float* d, const uint32_t* a, const uint32_t* b,
                                         const float* c) {
    asm volatile(
        "mma.sync.aligned.m16n8k8.row.col.f32.tf32.tf32.f32 "
        "{%0,%1,%2,%3}, {%4,%5,%6,%7}, {%8,%9}, {%10,%11,%12,%13};\n"
        : "=f"(d[0]), "=f"(d[1]), "=f"(d[2]), "=f"(d[3])
        : "r"(a[0]), "r"(a[1]), "r"(a[2]), "r"(a[3]),
          "r"(b[0]), "r"(b[1]),
          "f"(c[0]), "f"(c[1]), "f"(c[2]), "f"(c[3]));
}

// ---------------------------------------------------------------------------
// tf32 tensor-core GEMM:  C = alpha * A x op(B) + epilogue
//   A: [M,K] row-major;  op(B): transB ? B[N,K] : B[K,N]
//   Tiles: 128x128x16, 256 threads, double-buffered smem, tf32 cvt at store.
//   K must be a multiple of 16 (true for all call sites).
// ---------------------------------------------------------------------------
#define GBM 128
#define GBN 128
#define GBK 16
#define APITCH 20
#define BPITCH 132

__global__ void __launch_bounds__(256, 1) gemm_tf32_kernel(
    int M, int N, int K,
    const float* __restrict__ A, int lda, long long sA,
    const float* __restrict__ B, int ldb, long long sB, int transB,
    float* __restrict__ C, int ldc, long long sC,
    float alpha,
    const float* __restrict__ bias,
    const float* __restrict__ biasScale,
    int relu,
    const float* __restrict__ addC,
    const float* __restrict__ rowMask)
{
    __shared__ uint32_t As[2][GBM * APITCH];   // [m][k], pitch 20
    __shared__ uint32_t Bs[2][GBK * BPITCH];   // [k][n], pitch 132

    const int bz = blockIdx.z;
    A += (long long)bz * sA;
    B += (long long)bz * sB;
    C += (long long)bz * sC;

    const int bm = blockIdx.y * GBM;
    const int bn = blockIdx.x * GBN;
    const int t = threadIdx.x;
    const int wid = t >> 5;
    const int lane = t & 31;
    const int q = lane >> 2;
    const int r = lane & 3;
    const int wm = (wid & 1) * 64;   // warp row offset within tile
    const int wn = (wid >> 1) * 32;  // warp col offset

    float acc[4][4][4];
    #pragma unroll
    for (int mi = 0; mi < 4; mi++)
        #pragma unroll
        for (int ni = 0; ni < 4; ni++)
            #pragma unroll
            for (int e = 0; e < 4; e++) acc[mi][ni][e] = 0.0f;

    // prefetch registers
    float aPre[2][4];
    float bPre[2][4];

    // ---- A load indices: thread loads float4 at rows (t>>2) and (t>>2)+64 ----
    const int am = t >> 2;
    const int ak = (t & 3) << 2;
    // ---- B load indices ----
    const int bn4 = (t & 31) << 2;  // non-trans: col group
    const int bk = t >> 5;          // non-trans: k row (0..7)
    const int tn = t >> 2;          // trans: n row
    const int tk = (t & 3) << 2;    // trans: k group

    const bool fullN = (bn + GBN <= N);

    auto loadA = [&](int k0) {
        #pragma unroll
        for (int i = 0; i < 2; i++) {
            int gm = bm + am + 64 * i;
            if (gm < M) {
                const float4 v = *reinterpret_cast<const float4*>(A + (long long)gm * lda + k0 + ak);
                aPre[i][0] = v.x; aPre[i][1] = v.y; aPre[i][2] = v.z; aPre[i][3] = v.w;
            } else {
                aPre[i][0] = aPre[i][1] = aPre[i][2] = aPre[i][3] = 0.0f;
            }
        }
    };
    auto loadB = [&](int k0) {
        if (!transB) {
            #pragma unroll
            for (int i = 0; i < 2; i++) {
                int k = bk + 8 * i;
                if (fullN) {
                    const float4 v = *reinterpret_cast<const float4*>(B + (long long)(k0 + k) * ldb + bn + bn4);
                    bPre[i][0] = v.x; bPre[i][1] = v.y; bPre[i][2] = v.z; bPre[i][3] = v.w;
                } else {
                    #pragma unroll
                    for (int j = 0; j < 4; j++) {
                        int gn = bn + bn4 + j;
                        bPre[i][j] = (gn < N) ? B[(long long)(k0 + k) * ldb + gn] : 0.0f;
                    }
                }
            }
        } else {
            #pragma unroll
            for (int i = 0; i < 2; i++) {
                int gn = bn + tn + 64 * i;
                if (gn < N) {
                    const float4 v = *reinterpret_cast<const float4*>(B + (long long)gn * ldb + k0 + tk);
                    bPre[i][0] = v.x; bPre[i][1] = v.y; bPre[i][2] = v.z; bPre[i][3] = v.w;
                } else {
                    bPre[i][0] = bPre[i][1] = bPre[i][2] = bPre[i][3] = 0.0f;
                }
            }
        }
    };
    auto storeStage = [&](int s) {
        #pragma unroll
        for (int i = 0; i < 2; i++) {
            uint32_t* dst = &As[s][(am + 64 * i) * APITCH + ak];
            dst[0] = f2tf32(aPre[i][0]); dst[1] = f2tf32(aPre[i][1]);
            dst[2] = f2tf32(aPre[i][2]); dst[3] = f2tf32(aPre[i][3]);
        }
        if (!transB) {
            #pragma unroll
            for (int i = 0; i < 2; i++) {
                uint32_t* dst = &Bs[s][(bk + 8 * i) * BPITCH + bn4];
                dst[0] = f2tf32(bPre[i][0]); dst[1] = f2tf32(bPre[i][1]);
                dst[2] = f2tf32(bPre[i][2]); dst[3] = f2tf32(bPre[i][3]);
            }
        } else {
            #pragma unroll
            for (int i = 0; i < 2; i++) {
                int n = tn + 64 * i;
                #pragma unroll
                for (int j = 0; j < 4; j++)
                    Bs[s][(tk + j) * BPITCH + n] = f2tf32(bPre[i][j]);
            }
        }
    };
    auto computeStage = [&](int s) {
        #pragma unroll
        for (int ks = 0; ks < 2; ks++) {
            const int kb = ks * 8;
            uint32_t af[4][4], bf[4][2];
            #pragma unroll
            for (int mi = 0; mi < 4; mi++) {
                int row0 = wm + mi * 16 + q;
                af[mi][0] = As[s][row0 * APITCH + kb + r];
                af[mi][1] = As[s][(row0 + 8) * APITCH + kb + r];
                af[mi][2] = As[s][row0 * APITCH + kb + r + 4];
                af[mi][3] = As[s][(row0 + 8) * APITCH + kb + r + 4];
            }
            #pragma unroll
            for (int ni = 0; ni < 4; ni++) {
                int col = wn + ni * 8 + q;
                bf[ni][0] = Bs[s][(kb + r) * BPITCH + col];
                bf[ni][1] = Bs[s][(kb + r + 4) * BPITCH + col];
            }
            #pragma unroll
            for (int mi = 0; mi < 4; mi++)
                #pragma unroll
                for (int ni = 0; ni < 4; ni++)
                    mma_tf32(acc[mi][ni], af[mi], bf[ni], acc[mi][ni]);
        }
    };

    const int ntiles = K / GBK;
    loadA(0); loadB(0);
    storeStage(0);
    __syncthreads();
    for (int it = 0; it < ntiles; it++) {
        const int s = it & 1;
        if (it + 1 < ntiles) { loadA((it + 1) * GBK); loadB((it + 1) * GBK); }
        computeStage(s);
        if (it + 1 < ntiles) storeStage(s ^ 1);
        __syncthreads();
    }

    // ---- epilogue ----
    #pragma unroll
    for (int mi = 0; mi < 4; mi++) {
        #pragma unroll
        for (int ni = 0; ni < 4; ni++) {
            #pragma unroll
            for (int half = 0; half < 2; half++) {
                int gm = bm + wm + mi * 16 + q + half * 8;
                if (gm >= M) continue;
                float bs = biasScale ? biasScale[gm] : 1.0f;
                float rm = rowMask ? rowMask[gm] : 1.0f;
                #pragma unroll
                for (int j = 0; j < 2; j++) {
                    int gn = bn + wn + ni * 8 + 2 * r + j;
                    if (gn >= N) continue;
                    float v = acc[mi][ni][half * 2 + j] * alpha;
                    if (bias) v += bias[gn] * bs;
                    if (relu) v = fmaxf(v, 0.0f);
                    if (addC) v += addC[(long long)gm * ldc + gn];
                    v *= rm;
                    C[(long long)gm * ldc + gn] = v;
                }
            }
        }
    }
}

// ---------------------------------------------------------------------------
// Block reductions
// ---------------------------------------------------------------------------
__device__ __forceinline__ float blockReduceSum(float v, float* red) {
    #pragma unroll
    for (int o = 16; o > 0; o >>= 1) v += __shfl_xor_sync(0xffffffffu, v, o);
    int w = threadIdx.x >> 5;
    if ((threadIdx.x & 31) == 0) red[w] = v;
    __syncthreads();
    float r;
    if (threadIdx.x < 32) {
        r = (threadIdx.x < (blockDim.x >> 5)) ? red[threadIdx.x] : 0.0f;
        #pragma unroll
        for (int o = 16; o > 0; o >>= 1) r += __shfl_xor_sync(0xffffffffu, r, o);
        if (threadIdx.x == 0) red[0] = r;
    }
    __syncthreads();
    r = red[0];
    __syncthreads();
    return r;
}

__device__ __forceinline__ float blockReduceMax(float v, float* red) {
    #pragma unroll
    for (int o = 16; o > 0; o >>= 1) v = fmaxf(v, __shfl_xor_sync(0xffffffffu, v, o));
    int w = threadIdx.x >> 5;
    if ((threadIdx.x & 31) == 0) red[w] = v;
    __syncthreads();
    float r;
    if (threadIdx.x < 32) {
        r = (threadIdx.x < (blockDim.x >> 5)) ? red[threadIdx.x] : -1e30f;
        #pragma unroll
        for (int o = 16; o > 0; o >>= 1) r = fmaxf(r, __shfl_xor_sync(0xffffffffu, r, o));
        if (threadIdx.x == 0) red[0] = r;
    }
    __syncthreads();
    r = red[0];
    __syncthreads();
    return r;
}

// ---------------------------------------------------------------------------
// Row softmax, in place. grid = (rows, batch), 256 threads. Templated iters.
// ---------------------------------------------------------------------------
template <int NITER>
__global__ void softmax_kernel(float* __restrict__ S, int N, int ld, long long bStride)
{
    float* row = S + (long long)blockIdx.y * bStride + (long long)blockIdx.x * ld;
    int tid = threadIdx.x;
    float v[NITER];
    float mx = -1e30f;
    #pragma unroll
    for (int i = 0; i < NITER; i++) {
        int idx = tid + (i << 8);
        v[i] = (idx < N) ? row[idx] : -1e30f;
        mx = fmaxf(mx, v[i]);
    }
    __shared__ float red[8];
    mx = blockReduceMax(mx, red);
    float s = 0.0f;
    #pragma unroll
    for (int i = 0; i < NITER; i++) {
        v[i] = __expf(v[i] - mx);
        int idx = tid + (i << 8);
        if (idx >= N) v[i] = 0.0f;
        s += v[i];
    }
    s = blockReduceSum(s, red);
    float inv = 1.0f / s;
    #pragma unroll
    for (int i = 0; i < NITER; i++) {
        int idx = tid + (i << 8);
        if (idx < N) row[idx] = v[i] * inv;
    }
}

// ---------------------------------------------------------------------------
// out[row] = LN(a[row] + b[row]) * g + beta
// ---------------------------------------------------------------------------
__global__ void add_ln_kernel(const float* __restrict__ a, const float* __restrict__ b,
                              const float* __restrict__ g, const float* __restrict__ be,
                              float* __restrict__ out)
{
    long long row = blockIdx.x;
    const float* ar = a + row * CC;
    const float* br = b + row * CC;
    int tid = threadIdx.x;
    float x0 = ar[tid] + br[tid];
    float x1 = ar[tid + 256] + br[tid + 256];
    __shared__ float red[8];
    float mu = blockReduceSum(x0 + x1, red) * (1.0f / CC);
    float d0 = x0 - mu, d1 = x1 - mu;
    float var = blockReduceSum(d0 * d0 + d1 * d1, red) * (1.0f / CC);
    float rstd = rsqrtf(var + 1e-5f);
    out[row * CC + tid]       = d0 * rstd * g[tid] + be[tid];
    out[row * CC + tid + 256] = d1 * rstd * g[tid + 256] + be[tid + 256];
}

// ---------------------------------------------------------------------------
// Masked-mean neighbor aggregation
// ---------------------------------------------------------------------------
__global__ void agg_kernel(const float* __restrict__ X, int C,
                           const int* __restrict__ nbm,
                           const float* __restrict__ childMask,
                           float* __restrict__ out, float* __restrict__ coefOut, int P)
{
    long long idx = (long long)blockIdx.x * blockDim.x + threadIdx.x;
    if (idx >= (long long)P * C) return;
    int p = (int)(idx / C);
    int c = (int)(idx % C);
    float sum = 0.0f, den = 0.0f, wsum = 0.0f;
    #pragma unroll
    for (int f = 0; f < FAN; f++) {
        float nb = (float)nbm[p * FAN + f];
        den += nb;
        float w = nb * (childMask ? childMask[p * FAN + f] : 1.0f);
        wsum += w;
        sum += w * X[(long long)(p * FAN + f) * C + c];
    }
    den = fmaxf(den, 1.0f);
    out[(long long)p * C + c] = sum / den;
    if (coefOut && c == 0) coefOut[p] = wsum / den;
}

__global__ void concat_kernel(const float* __restrict__ a, const float* __restrict__ b,
                              float* __restrict__ out, int n)
{
    long long idx = (long long)blockIdx.x * blockDim.x + threadIdx.x;
    if (idx >= (long long)n * 2 * CC) return;
    int m = (int)(idx >> 10);
    int c = (int)(idx & 1023);
    out[idx] = (c < CC) ? a[(long long)m * CC + c] : b[(long long)m * CC + c - CC];
}

// ---------------------------------------------------------------------------
// Host-side orchestration
// ---------------------------------------------------------------------------
static void gemm(int M, int N, int K,
                 const float* A, int lda, long long sA,
                 const float* B, int ldb, long long sB, int transB,
                 float* C, int ldc, long long sC, int nbatch,
                 float alpha, const float* bias, const float* biasScale, int relu,
                 const float* addC, const float* rowMask)
{
    dim3 grid((N + GBN - 1) / GBN, (M + GBM - 1) / GBM, nbatch);
    gemm_tf32_kernel<<<grid, 256>>>(M, N, K, A, lda, sA, B, ldb, sB, transB,
                                    C, ldc, sC, alpha, bias, biasScale, relu, addC, rowMask);
}

struct Scratch {
    float *S1E, *S1N, *S0, *AGGF, *AGGC, *AGG, *CAT, *HL, *H1, *QKV, *SC, *ATTO, *ATT, *H2, *FF1;
};

static Scratch get_scratch() {
    Scratch s;
    void* p;
    cudaGetSymbolAddress(&p, g_S1E);  s.S1E  = (float*)p;
    cudaGetSymbolAddress(&p, g_S1N);  s.S1N  = (float*)p;
    cudaGetSymbolAddress(&p, g_S0);   s.S0   = (float*)p;
    cudaGetSymbolAddress(&p, g_AGGF); s.AGGF = (float*)p;
    cudaGetSymbolAddress(&p, g_AGGC); s.AGGC = (float*)p;
    cudaGetSymbolAddress(&p, g_AGG);  s.AGG  = (float*)p;
    cudaGetSymbolAddress(&p, g_CAT);  s.CAT  = (float*)p;
    cudaGetSymbolAddress(&p, g_HL);   s.HL   = (float*)p;
    cudaGetSymbolAddress(&p, g_H1);   s.H1   = (float*)p;
    cudaGetSymbolAddress(&p, g_QKV);  s.QKV  = (float*)p;
    cudaGetSymbolAddress(&p, g_SC);   s.SC   = (float*)p;
    cudaGetSymbolAddress(&p, g_ATTO); s.ATTO = (float*)p;
    cudaGetSymbolAddress(&p, g_ATT);  s.ATT  = (float*)p;
    cudaGetSymbolAddress(&p, g_H2);   s.H2   = (float*)p;
    cudaGetSymbolAddress(&p, g_FF1);  s.FF1  = (float*)p;
    return s;
}

struct LayerW {
    const float *sageW, *sageB, *qkvW, *qkvB, *outW, *outB;
    const float *n1g, *n1b, *n2g, *n2b, *ffnW1, *ffnB1, *ffnW2, *ffnB2;
};

static void block_forward(int n, const float* sf, const float* agg, float* outState,
                          const float* rowMask, const LayerW& w, const Scratch& s)
{
    const float scale = 0.08838834764831845f;  // 1/sqrt(128)

    concat_kernel<<<(int)(((long long)n * 2 * CC + 255) / 256), 256>>>(sf, agg, s.CAT, n);
    gemm(n, CC, 2 * CC, s.CAT, 2 * CC, 0, w.sageW, 2 * CC, 0, 1,
         s.HL, CC, 0, 1, 1.0f, w.sageB, nullptr, 0, nullptr, nullptr);
    add_ln_kernel<<<n, 256>>>(sf, s.HL, w.n1g, w.n1b, s.H1);

    gemm(n, 3 * CC, CC, s.H1, CC, 0, w.qkvW, CC, 0, 1,
         s.QKV, 3 * CC, 0, 1, 1.0f, w.qkvB, nullptr, 0, nullptr, nullptr);
    gemm(n, n, DH, s.QKV, 3 * CC, DH, s.QKV + CC, 3 * CC, DH, 1,
         s.SC, n, (long long)n * n, HH, scale, nullptr, nullptr, 0, nullptr, nullptr);
    {
        dim3 grid(n, HH);
        if (n == N1) softmax_kernel<16><<<grid, 256>>>(s.SC, n, n, (long long)n * n);
        else         softmax_kernel<1><<<grid, 256>>>(s.SC, n, n, (long long)n * n);
    }
    gemm(n, DH, n, s.SC, n, (long long)n * n, s.QKV + 2 * CC, 3 * CC, DH, 0,
         s.ATTO, CC, DH, HH, 1.0f, nullptr, nullptr, 0, nullptr, nullptr);
    gemm(n, CC, CC, s.ATTO, CC, 0, w.outW, CC, 0, 1,
         s.ATT, CC, 0, 1, 1.0f, w.outB, nullptr, 0, nullptr, nullptr);
    add_ln_kernel<<<n, 256>>>(s.H1, s.ATT, w.n2g, w.n2b, s.H2);

    gemm(n, 2 * CC, CC, s.H2, CC, 0, w.ffnW1, CC, 0, 1,
         s.FF1, 2 * CC, 0, 1, 1.0f, w.ffnB1, nullptr, 1, nullptr, nullptr);
    gemm(n, CC, 2 * CC, s.FF1, 2 * CC, 0, w.ffnW2, 2 * CC, 0, 1,
         outState, CC, 0, 1, 1.0f, w.ffnB2, nullptr, 0, s.H2, rowMask);
}

extern "C" void kernel_launch(void* const* d_in, const int* in_sizes, int n_in,
                              void* d_out, int out_size)
{
    const float* feats0  = (const float*)d_in[0];
    const float* feats1  = (const float*)d_in[1];
    const float* feats2  = (const float*)d_in[2];
    const float* nmask0  = (const float*)d_in[3];
    const float* nmask1  = (const float*)d_in[4];
    const float* nmask2  = (const float*)d_in[5];
    const int*   nbmask0 = (const int*)d_in[6];
    const int*   nbmask1 = (const int*)d_in[7];
    const float* emb_w   = (const float*)d_in[8];
    const float* emb_b   = (const float*)d_in[9];
    const float* sage_w  = (const float*)d_in[10];
    const float* sage_b  = (const float*)d_in[11];
    const float* qkv_w   = (const float*)d_in[12];
    const float* qkv_b   = (const float*)d_in[13];
    const float* out_w   = (const float*)d_in[14];
    const float* out_b   = (const float*)d_in[15];
    const float* n1_g    = (const float*)d_in[16];
    const float* n1_b    = (const float*)d_in[17];
    const float* n2_g    = (const float*)d_in[18];
    const float* n2_b    = (const float*)d_in[19];
    const float* ffn_w1  = (const float*)d_in[20];
    const float* ffn_b1  = (const float*)d_in[21];
    const float* ffn_w2  = (const float*)d_in[22];
    const float* ffn_b2  = (const float*)d_in[23];
    const float* cls_w   = (const float*)d_in[24];
    const float* cls_b   = (const float*)d_in[25];
    float* out = (float*)d_out;

    Scratch s = get_scratch();

    LayerW w[NL];
    for (int li = 0; li < NL; li++) {
        w[li].sageW = sage_w + (long long)li * CC * 2 * CC;
        w[li].sageB = sage_b + li * CC;
        w[li].qkvW  = qkv_w  + (long long)li * 3 * CC * CC;
        w[li].qkvB  = qkv_b  + li * 3 * CC;
        w[li].outW  = out_w  + (long long)li * CC * CC;
        w[li].outB  = out_b  + li * CC;
        w[li].n1g   = n1_g + li * CC;  w[li].n1b = n1_b + li * CC;
        w[li].n2g   = n2_g + li * CC;  w[li].n2b = n2_b + li * CC;
        w[li].ffnW1 = ffn_w1 + (long long)li * 2 * CC * CC;
        w[li].ffnB1 = ffn_b1 + li * 2 * CC;
        w[li].ffnW2 = ffn_w2 + (long long)li * CC * 2 * CC;
        w[li].ffnB2 = ffn_b2 + li * CC;
    }

    // ---- embeddings (depth 0 and 1), masked ----
    gemm(N0, CC, INDIM, feats0, INDIM, 0, emb_w, INDIM, 0, 1,
         s.S0, CC, 0, 1, 1.0f, emb_b, nullptr, 0, nullptr, nmask0);
    gemm(N1, CC, INDIM, feats1, INDIM, 0, emb_w, INDIM, 0, 1,
         s.S1E, CC, 0, 1, 1.0f, emb_b, nullptr, 0, nullptr, nmask1);

    // ---- depth-2: aggregate RAW features, then one embedding GEMM ----
    agg_kernel<<<(int)(((long long)N1 * INDIM + 255) / 256), 256>>>(
        feats2, INDIM, nbmask1, nmask2, s.AGGF, s.AGGC, N1);
    gemm(N1, CC, INDIM, s.AGGF, INDIM, 0, emb_w, INDIM, 0, 1,
         s.AGG, CC, 0, 1, 1.0f, emb_b, s.AGGC, 0, nullptr, nullptr);

    // ---- layer 0, depth 1 (n = 4096) ----
    block_forward(N1, s.S1E, s.AGG, s.S1N, nmask1, w[0], s);

    // ---- layer 0, depth 0 ----
    agg_kernel<<<(int)(((long long)N0 * CC + 255) / 256), 256>>>(
        s.S1E, CC, nbmask0, nullptr, s.AGG, nullptr, N0);
    block_forward(N0, s.S0, s.AGG, s.S0, nmask0, w[0], s);

    // ---- layer 1, depth 0 ----
    agg_kernel<<<(int)(((long long)N0 * CC + 255) / 256), 256>>>(
        s.S1N, CC, nbmask0, nullptr, s.AGG, nullptr, N0);
    block_forward(N0, s.S0, s.AGG, s.S0, nmask0, w[1], s);

    // ---- classifier ----
    gemm(N0, NC, CC, s.S0, CC, 0, cls_w, CC, 0, 1,
         out, NC, 0, 1, 1.0f, cls_b, nullptr, 0, nullptr, nullptr);
}

// round 3
// speedup vs baseline: 2.5236x; 1.1220x over previous
#include <cuda_runtime.h>
#include <math.h>
#include <stdint.h>

// ---------------------------------------------------------------------------
// Problem constants
// ---------------------------------------------------------------------------
#define NL 2
#define HH 4
#define CC 512
#define INDIM 256
#define FAN 16
#define NC 47
#define DH 128
#define N0 256
#define N1 4096
#define N2 65536

// ---------------------------------------------------------------------------
// Device scratch
// ---------------------------------------------------------------------------
__device__ float g_S1E[N1 * CC];
__device__ float g_S1N[N1 * CC];
__device__ float g_S0[N0 * CC];
__device__ float g_AGGF[N1 * INDIM];
__device__ float g_AGGC[N1];
__device__ float g_AGG[N1 * CC];
__device__ float g_CAT[N1 * 2 * CC];
__device__ float g_HL[N1 * CC];
__device__ float g_H1[N1 * CC];
__device__ float g_QKV[N1 * 3 * CC];
__device__ float g_ATTO[N1 * CC];
__device__ float g_ATT[N1 * CC];
__device__ float g_H2[N1 * CC];
__device__ float g_FF1[N1 * 2 * CC];

// ---------------------------------------------------------------------------
// tf32 helpers
// ---------------------------------------------------------------------------
__device__ __forceinline__ uint32_t f2tf32(float f) {
    uint32_t u;
    asm("cvt.rna.tf32.f32 %0, %1;" : "=r"(u) : "f"(f));
    return u;
}

__device__ __forceinline__ void mma_tf32(float* d, const uint32_t* a, const uint32_t* b,
                                         const float* c) {
    asm volatile(
        "mma.sync.aligned.m16n8k8.row.col.f32.tf32.tf32.f32 "
        "{%0,%1,%2,%3}, {%4,%5,%6,%7}, {%8,%9}, {%10,%11,%12,%13};\n"
        : "=f"(d[0]), "=f"(d[1]), "=f"(d[2]), "=f"(d[3])
        : "r"(a[0]), "r"(a[1]), "r"(a[2]), "r"(a[3]),
          "r"(b[0]), "r"(b[1]),
          "f"(c[0]), "f"(c[1]), "f"(c[2]), "f"(c[3]));
}

// ---------------------------------------------------------------------------
// tf32 tensor-core GEMM (as in R2): C = alpha * A x op(B) + epilogue
// ---------------------------------------------------------------------------
#define GBM 128
#define GBN 128
#define GBK 16
#define APITCH 20
#define BPITCH 132

__global__ void __launch_bounds__(256, 1) gemm_tf32_kernel(
    int M, int N, int K,
    const float* __restrict__ A, int lda, long long sA,
    const float* __restrict__ B, int ldb, long long sB, int transB,
    float* __restrict__ C, int ldc, long long sC,
    float alpha,
    const float* __restrict__ bias,
    const float* __restrict__ biasScale,
    int relu,
    const float* __restrict__ addC,
    const float* __restrict__ rowMask)
{
    __shared__ uint32_t As[2][GBM * APITCH];
    __shared__ uint32_t Bs[2][GBK * BPITCH];

    const int bz = blockIdx.z;
    A += (long long)bz * sA;
    B += (long long)bz * sB;
    C += (long long)bz * sC;

    const int bm = blockIdx.y * GBM;
    const int bn = blockIdx.x * GBN;
    const int t = threadIdx.x;
    const int wid = t >> 5;
    const int lane = t & 31;
    const int q = lane >> 2;
    const int r = lane & 3;
    const int wm = (wid & 1) * 64;
    const int wn = (wid >> 1) * 32;

    float acc[4][4][4];
    #pragma unroll
    for (int mi = 0; mi < 4; mi++)
        #pragma unroll
        for (int ni = 0; ni < 4; ni++)
            #pragma unroll
            for (int e = 0; e < 4; e++) acc[mi][ni][e] = 0.0f;

    float aPre[2][4];
    float bPre[2][4];

    const int am = t >> 2;
    const int ak = (t & 3) << 2;
    const int bn4 = (t & 31) << 2;
    const int bk = t >> 5;
    const int tn = t >> 2;
    const int tk = (t & 3) << 2;

    const bool fullN = (bn + GBN <= N);

    auto loadA = [&](int k0) {
        #pragma unroll
        for (int i = 0; i < 2; i++) {
            int gm = bm + am + 64 * i;
            if (gm < M) {
                const float4 v = *reinterpret_cast<const float4*>(A + (long long)gm * lda + k0 + ak);
                aPre[i][0] = v.x; aPre[i][1] = v.y; aPre[i][2] = v.z; aPre[i][3] = v.w;
            } else {
                aPre[i][0] = aPre[i][1] = aPre[i][2] = aPre[i][3] = 0.0f;
            }
        }
    };
    auto loadB = [&](int k0) {
        if (!transB) {
            #pragma unroll
            for (int i = 0; i < 2; i++) {
                int k = bk + 8 * i;
                if (fullN) {
                    const float4 v = *reinterpret_cast<const float4*>(B + (long long)(k0 + k) * ldb + bn + bn4);
                    bPre[i][0] = v.x; bPre[i][1] = v.y; bPre[i][2] = v.z; bPre[i][3] = v.w;
                } else {
                    #pragma unroll
                    for (int j = 0; j < 4; j++) {
                        int gn = bn + bn4 + j;
                        bPre[i][j] = (gn < N) ? B[(long long)(k0 + k) * ldb + gn] : 0.0f;
                    }
                }
            }
        } else {
            #pragma unroll
            for (int i = 0; i < 2; i++) {
                int gn = bn + tn + 64 * i;
                if (gn < N) {
                    const float4 v = *reinterpret_cast<const float4*>(B + (long long)gn * ldb + k0 + tk);
                    bPre[i][0] = v.x; bPre[i][1] = v.y; bPre[i][2] = v.z; bPre[i][3] = v.w;
                } else {
                    bPre[i][0] = bPre[i][1] = bPre[i][2] = bPre[i][3] = 0.0f;
                }
            }
        }
    };
    auto storeStage = [&](int s) {
        #pragma unroll
        for (int i = 0; i < 2; i++) {
            uint32_t* dst = &As[s][(am + 64 * i) * APITCH + ak];
            dst[0] = f2tf32(aPre[i][0]); dst[1] = f2tf32(aPre[i][1]);
            dst[2] = f2tf32(aPre[i][2]); dst[3] = f2tf32(aPre[i][3]);
        }
        if (!transB) {
            #pragma unroll
            for (int i = 0; i < 2; i++) {
                uint32_t* dst = &Bs[s][(bk + 8 * i) * BPITCH + bn4];
                dst[0] = f2tf32(bPre[i][0]); dst[1] = f2tf32(bPre[i][1]);
                dst[2] = f2tf32(bPre[i][2]); dst[3] = f2tf32(bPre[i][3]);
            }
        } else {
            #pragma unroll
            for (int i = 0; i < 2; i++) {
                int n = tn + 64 * i;
                #pragma unroll
                for (int j = 0; j < 4; j++)
                    Bs[s][(tk + j) * BPITCH + n] = f2tf32(bPre[i][j]);
            }
        }
    };
    auto computeStage = [&](int s) {
        #pragma unroll
        for (int ks = 0; ks < 2; ks++) {
            const int kb = ks * 8;
            uint32_t af[4][4], bf[4][2];
            #pragma unroll
            for (int mi = 0; mi < 4; mi++) {
                int row0 = wm + mi * 16 + q;
                af[mi][0] = As[s][row0 * APITCH + kb + r];
                af[mi][1] = As[s][(row0 + 8) * APITCH + kb + r];
                af[mi][2] = As[s][row0 * APITCH + kb + r + 4];
                af[mi][3] = As[s][(row0 + 8) * APITCH + kb + r + 4];
            }
            #pragma unroll
            for (int ni = 0; ni < 4; ni++) {
                int col = wn + ni * 8 + q;
                bf[ni][0] = Bs[s][(kb + r) * BPITCH + col];
                bf[ni][1] = Bs[s][(kb + r + 4) * BPITCH + col];
            }
            #pragma unroll
            for (int mi = 0; mi < 4; mi++)
                #pragma unroll
                for (int ni = 0; ni < 4; ni++)
                    mma_tf32(acc[mi][ni], af[mi], bf[ni], acc[mi][ni]);
        }
    };

    const int ntiles = K / GBK;
    loadA(0); loadB(0);
    storeStage(0);
    __syncthreads();
    for (int it = 0; it < ntiles; it++) {
        const int s = it & 1;
        if (it + 1 < ntiles) { loadA((it + 1) * GBK); loadB((it + 1) * GBK); }
        computeStage(s);
        if (it + 1 < ntiles) storeStage(s ^ 1);
        __syncthreads();
    }

    #pragma unroll
    for (int mi = 0; mi < 4; mi++) {
        #pragma unroll
        for (int ni = 0; ni < 4; ni++) {
            #pragma unroll
            for (int half = 0; half < 2; half++) {
                int gm = bm + wm + mi * 16 + q + half * 8;
                if (gm >= M) continue;
                float bs = biasScale ? biasScale[gm] : 1.0f;
                float rm = rowMask ? rowMask[gm] : 1.0f;
                #pragma unroll
                for (int j = 0; j < 2; j++) {
                    int gn = bn + wn + ni * 8 + 2 * r + j;
                    if (gn >= N) continue;
                    float v = acc[mi][ni][half * 2 + j] * alpha;
                    if (bias) v += bias[gn] * bs;
                    if (relu) v = fmaxf(v, 0.0f);
                    if (addC) v += addC[(long long)gm * ldc + gn];
                    v *= rm;
                    C[(long long)gm * ldc + gn] = v;
                }
            }
        }
    }
}

// ---------------------------------------------------------------------------
// Flash attention (tf32 mma, online softmax). One CTA = 64 query rows x 1 head.
//   QKV: [n][3*CC] with Q at col h*DH, K at CC + h*DH, V at 2*CC + h*DH.
//   O:   [n][CC] at col h*DH.
// 128 threads = 4 warps; warp owns 16 query rows. KV tiles of 64.
// ---------------------------------------------------------------------------
#define FTM 64
#define FTN 64
#define FPITCH 132
#define PPITCH 68
#define FLASH_SMEM ((3 * FTM * FPITCH + FTM * PPITCH) * 4)

__global__ void __launch_bounds__(128) flash_kernel(
    const float* __restrict__ QKV, float* __restrict__ O, int n)
{
    extern __shared__ float sm[];
    float* sQ = sm;
    float* sK = sQ + FTM * FPITCH;
    float* sV = sK + FTN * FPITCH;
    float* sP = sV + FTN * FPITCH;
    uint32_t* uQ = (uint32_t*)sQ;
    uint32_t* uK = (uint32_t*)sK;
    uint32_t* uV = (uint32_t*)sV;
    uint32_t* uP = (uint32_t*)sP;

    const int t = threadIdx.x;
    const int warp = t >> 5;
    const int lane = t & 31;
    const int q = lane >> 2;
    const int r = lane & 3;
    const int head = blockIdx.y;
    const int qbase = blockIdx.x * FTM;
    const int row0 = warp * 16 + q;

    const float scale = 0.08838834764831845f;  // 1/sqrt(128)

    // ---- load Q tile (64 x 128) ----
    #pragma unroll
    for (int i = 0; i < 16; i++) {
        int idx = t + i * 128;
        int row = idx >> 5;       // 32 float4 per row
        int c4 = idx & 31;
        const float4 v = *reinterpret_cast<const float4*>(
            QKV + (long long)(qbase + row) * (3 * CC) + head * DH + c4 * 4);
        uint32_t* d = uQ + row * FPITCH + c4 * 4;
        d[0] = f2tf32(v.x); d[1] = f2tf32(v.y); d[2] = f2tf32(v.z); d[3] = f2tf32(v.w);
    }

    float oacc[16][4];
    #pragma unroll
    for (int df = 0; df < 16; df++)
        #pragma unroll
        for (int e = 0; e < 4; e++) oacc[df][e] = 0.0f;
    float m0 = -1e30f, m1 = -1e30f, l0 = 0.0f, l1 = 0.0f;

    const int ntiles = n / FTN;
    for (int kt = 0; kt < ntiles; kt++) {
        __syncthreads();
        // ---- load K, V tiles ----
        #pragma unroll
        for (int i = 0; i < 16; i++) {
            int idx = t + i * 128;
            int row = idx >> 5;
            int c4 = idx & 31;
            long long gro = (long long)(kt * FTN + row) * (3 * CC) + head * DH + c4 * 4;
            const float4 kv = *reinterpret_cast<const float4*>(QKV + gro + CC);
            uint32_t* dk = uK + row * FPITCH + c4 * 4;
            dk[0] = f2tf32(kv.x); dk[1] = f2tf32(kv.y); dk[2] = f2tf32(kv.z); dk[3] = f2tf32(kv.w);
            const float4 vv = *reinterpret_cast<const float4*>(QKV + gro + 2 * CC);
            uint32_t* dv = uV + row * FPITCH + c4 * 4;
            dv[0] = f2tf32(vv.x); dv[1] = f2tf32(vv.y); dv[2] = f2tf32(vv.z); dv[3] = f2tf32(vv.w);
        }
        __syncthreads();

        // ---- S = Q @ K^T ----
        float sacc[8][4];
        #pragma unroll
        for (int nf = 0; nf < 8; nf++)
            #pragma unroll
            for (int e = 0; e < 4; e++) sacc[nf][e] = 0.0f;
        #pragma unroll
        for (int kc = 0; kc < 16; kc++) {
            const int kb = kc * 8;
            uint32_t af[4];
            af[0] = uQ[row0 * FPITCH + kb + r];
            af[1] = uQ[(row0 + 8) * FPITCH + kb + r];
            af[2] = uQ[row0 * FPITCH + kb + r + 4];
            af[3] = uQ[(row0 + 8) * FPITCH + kb + r + 4];
            #pragma unroll
            for (int nf = 0; nf < 8; nf++) {
                const int col = nf * 8 + q;
                uint32_t bf[2];
                bf[0] = uK[col * FPITCH + kb + r];
                bf[1] = uK[col * FPITCH + kb + r + 4];
                mma_tf32(sacc[nf], af, bf, sacc[nf]);
            }
        }

        // ---- online softmax (rows q and q+8 of this warp's 16) ----
        float tm0 = -1e30f, tm1 = -1e30f;
        #pragma unroll
        for (int nf = 0; nf < 8; nf++) {
            sacc[nf][0] *= scale; sacc[nf][1] *= scale;
            sacc[nf][2] *= scale; sacc[nf][3] *= scale;
            tm0 = fmaxf(tm0, fmaxf(sacc[nf][0], sacc[nf][1]));
            tm1 = fmaxf(tm1, fmaxf(sacc[nf][2], sacc[nf][3]));
        }
        tm0 = fmaxf(tm0, __shfl_xor_sync(0xffffffffu, tm0, 1));
        tm0 = fmaxf(tm0, __shfl_xor_sync(0xffffffffu, tm0, 2));
        tm1 = fmaxf(tm1, __shfl_xor_sync(0xffffffffu, tm1, 1));
        tm1 = fmaxf(tm1, __shfl_xor_sync(0xffffffffu, tm1, 2));
        const float nm0 = fmaxf(m0, tm0);
        const float nm1 = fmaxf(m1, tm1);
        const float cor0 = __expf(m0 - nm0);
        const float cor1 = __expf(m1 - nm1);
        m0 = nm0; m1 = nm1;

        float ts0 = 0.0f, ts1 = 0.0f;
        #pragma unroll
        for (int nf = 0; nf < 8; nf++) {
            const float p0 = __expf(sacc[nf][0] - m0);
            const float p1 = __expf(sacc[nf][1] - m0);
            const float p2 = __expf(sacc[nf][2] - m1);
            const float p3 = __expf(sacc[nf][3] - m1);
            ts0 += p0 + p1;
            ts1 += p2 + p3;
            const int colb = nf * 8 + 2 * r;
            uP[row0 * PPITCH + colb]           = f2tf32(p0);
            uP[row0 * PPITCH + colb + 1]       = f2tf32(p1);
            uP[(row0 + 8) * PPITCH + colb]     = f2tf32(p2);
            uP[(row0 + 8) * PPITCH + colb + 1] = f2tf32(p3);
        }
        ts0 += __shfl_xor_sync(0xffffffffu, ts0, 1);
        ts0 += __shfl_xor_sync(0xffffffffu, ts0, 2);
        ts1 += __shfl_xor_sync(0xffffffffu, ts1, 1);
        ts1 += __shfl_xor_sync(0xffffffffu, ts1, 2);
        l0 = l0 * cor0 + ts0;
        l1 = l1 * cor1 + ts1;

        #pragma unroll
        for (int df = 0; df < 16; df++) {
            oacc[df][0] *= cor0; oacc[df][1] *= cor0;
            oacc[df][2] *= cor1; oacc[df][3] *= cor1;
        }
        __syncwarp();

        // ---- O += P @ V ----
        #pragma unroll
        for (int kc = 0; kc < 8; kc++) {
            const int kb = kc * 8;
            uint32_t af[4];
            af[0] = uP[row0 * PPITCH + kb + r];
            af[1] = uP[(row0 + 8) * PPITCH + kb + r];
            af[2] = uP[row0 * PPITCH + kb + r + 4];
            af[3] = uP[(row0 + 8) * PPITCH + kb + r + 4];
            #pragma unroll
            for (int df = 0; df < 16; df++) {
                uint32_t bf[2];
                bf[0] = uV[(kb + r) * FPITCH + df * 8 + q];
                bf[1] = uV[(kb + r + 4) * FPITCH + df * 8 + q];
                mma_tf32(oacc[df], af, bf, oacc[df]);
            }
        }
    }

    // ---- epilogue: O /= l, write [n][CC] ----
    const float inv0 = 1.0f / l0;
    const float inv1 = 1.0f / l1;
    #pragma unroll
    for (int df = 0; df < 16; df++) {
        const int gc = head * DH + df * 8 + 2 * r;
        O[(long long)(qbase + row0) * CC + gc]           = oacc[df][0] * inv0;
        O[(long long)(qbase + row0) * CC + gc + 1]       = oacc[df][1] * inv0;
        O[(long long)(qbase + row0 + 8) * CC + gc]       = oacc[df][2] * inv1;
        O[(long long)(qbase + row0 + 8) * CC + gc + 1]   = oacc[df][3] * inv1;
    }
}

// ---------------------------------------------------------------------------
// Block reductions
// ---------------------------------------------------------------------------
__device__ __forceinline__ float blockReduceSum(float v, float* red) {
    #pragma unroll
    for (int o = 16; o > 0; o >>= 1) v += __shfl_xor_sync(0xffffffffu, v, o);
    int w = threadIdx.x >> 5;
    if ((threadIdx.x & 31) == 0) red[w] = v;
    __syncthreads();
    float r;
    if (threadIdx.x < 32) {
        r = (threadIdx.x < (blockDim.x >> 5)) ? red[threadIdx.x] : 0.0f;
        #pragma unroll
        for (int o = 16; o > 0; o >>= 1) r += __shfl_xor_sync(0xffffffffu, r, o);
        if (threadIdx.x == 0) red[0] = r;
    }
    __syncthreads();
    r = red[0];
    __syncthreads();
    return r;
}

// ---------------------------------------------------------------------------
// out[row] = LN(a[row] + b[row]) * g + beta
// ---------------------------------------------------------------------------
__global__ void add_ln_kernel(const float* __restrict__ a, const float* __restrict__ b,
                              const float* __restrict__ g, const float* __restrict__ be,
                              float* __restrict__ out)
{
    long long row = blockIdx.x;
    const float* ar = a + row * CC;
    const float* br = b + row * CC;
    int tid = threadIdx.x;
    float x0 = ar[tid] + br[tid];
    float x1 = ar[tid + 256] + br[tid + 256];
    __shared__ float red[8];
    float mu = blockReduceSum(x0 + x1, red) * (1.0f / CC);
    float d0 = x0 - mu, d1 = x1 - mu;
    float var = blockReduceSum(d0 * d0 + d1 * d1, red) * (1.0f / CC);
    float rstd = rsqrtf(var + 1e-5f);
    out[row * CC + tid]       = d0 * rstd * g[tid] + be[tid];
    out[row * CC + tid + 256] = d1 * rstd * g[tid + 256] + be[tid + 256];
}

// ---------------------------------------------------------------------------
// Masked-mean neighbor aggregation
// ---------------------------------------------------------------------------
__global__ void agg_kernel(const float* __restrict__ X, int C,
                           const int* __restrict__ nbm,
                           const float* __restrict__ childMask,
                           float* __restrict__ out, float* __restrict__ coefOut, int P)
{
    long long idx = (long long)blockIdx.x * blockDim.x + threadIdx.x;
    if (idx >= (long long)P * C) return;
    int p = (int)(idx / C);
    int c = (int)(idx % C);
    float sum = 0.0f, den = 0.0f, wsum = 0.0f;
    #pragma unroll
    for (int f = 0; f < FAN; f++) {
        float nb = (float)nbm[p * FAN + f];
        den += nb;
        float w = nb * (childMask ? childMask[p * FAN + f] : 1.0f);
        wsum += w;
        sum += w * X[(long long)(p * FAN + f) * C + c];
    }
    den = fmaxf(den, 1.0f);
    out[(long long)p * C + c] = sum / den;
    if (coefOut && c == 0) coefOut[p] = wsum / den;
}

__global__ void concat_kernel(const float* __restrict__ a, const float* __restrict__ b,
                              float* __restrict__ out, int n)
{
    long long idx = (long long)blockIdx.x * blockDim.x + threadIdx.x;
    if (idx >= (long long)n * 2 * CC) return;
    int m = (int)(idx >> 10);
    int c = (int)(idx & 1023);
    out[idx] = (c < CC) ? a[(long long)m * CC + c] : b[(long long)m * CC + c - CC];
}

// ---------------------------------------------------------------------------
// Host-side orchestration
// ---------------------------------------------------------------------------
static void gemm(int M, int N, int K,
                 const float* A, int lda, long long sA,
                 const float* B, int ldb, long long sB, int transB,
                 float* C, int ldc, long long sC, int nbatch,
                 float alpha, const float* bias, const float* biasScale, int relu,
                 const float* addC, const float* rowMask)
{
    dim3 grid((N + GBN - 1) / GBN, (M + GBM - 1) / GBM, nbatch);
    gemm_tf32_kernel<<<grid, 256>>>(M, N, K, A, lda, sA, B, ldb, sB, transB,
                                    C, ldc, sC, alpha, bias, biasScale, relu, addC, rowMask);
}

struct Scratch {
    float *S1E, *S1N, *S0, *AGGF, *AGGC, *AGG, *CAT, *HL, *H1, *QKV, *ATTO, *ATT, *H2, *FF1;
};

static Scratch get_scratch() {
    Scratch s;
    void* p;
    cudaGetSymbolAddress(&p, g_S1E);  s.S1E  = (float*)p;
    cudaGetSymbolAddress(&p, g_S1N);  s.S1N  = (float*)p;
    cudaGetSymbolAddress(&p, g_S0);   s.S0   = (float*)p;
    cudaGetSymbolAddress(&p, g_AGGF); s.AGGF = (float*)p;
    cudaGetSymbolAddress(&p, g_AGGC); s.AGGC = (float*)p;
    cudaGetSymbolAddress(&p, g_AGG);  s.AGG  = (float*)p;
    cudaGetSymbolAddress(&p, g_CAT);  s.CAT  = (float*)p;
    cudaGetSymbolAddress(&p, g_HL);   s.HL   = (float*)p;
    cudaGetSymbolAddress(&p, g_H1);   s.H1   = (float*)p;
    cudaGetSymbolAddress(&p, g_QKV);  s.QKV  = (float*)p;
    cudaGetSymbolAddress(&p, g_ATTO); s.ATTO = (float*)p;
    cudaGetSymbolAddress(&p, g_ATT);  s.ATT  = (float*)p;
    cudaGetSymbolAddress(&p, g_H2);   s.H2   = (float*)p;
    cudaGetSymbolAddress(&p, g_FF1);  s.FF1  = (float*)p;
    return s;
}

struct LayerW {
    const float *sageW, *sageB, *qkvW, *qkvB, *outW, *outB;
    const float *n1g, *n1b, *n2g, *n2b, *ffnW1, *ffnB1, *ffnW2, *ffnB2;
};

static void block_forward(int n, const float* sf, const float* agg, float* outState,
                          const float* rowMask, const LayerW& w, const Scratch& s)
{
    concat_kernel<<<(int)(((long long)n * 2 * CC + 255) / 256), 256>>>(sf, agg, s.CAT, n);
    gemm(n, CC, 2 * CC, s.CAT, 2 * CC, 0, w.sageW, 2 * CC, 0, 1,
         s.HL, CC, 0, 1, 1.0f, w.sageB, nullptr, 0, nullptr, nullptr);
    add_ln_kernel<<<n, 256>>>(sf, s.HL, w.n1g, w.n1b, s.H1);

    gemm(n, 3 * CC, CC, s.H1, CC, 0, w.qkvW, CC, 0, 1,
         s.QKV, 3 * CC, 0, 1, 1.0f, w.qkvB, nullptr, 0, nullptr, nullptr);

    // fused flash attention: QK^T -> softmax -> @V, per head
    {
        dim3 grid(n / FTM, HH);
        flash_kernel<<<grid, 128, FLASH_SMEM>>>(s.QKV, s.ATTO, n);
    }

    gemm(n, CC, CC, s.ATTO, CC, 0, w.outW, CC, 0, 1,
         s.ATT, CC, 0, 1, 1.0f, w.outB, nullptr, 0, nullptr, nullptr);
    add_ln_kernel<<<n, 256>>>(s.H1, s.ATT, w.n2g, w.n2b, s.H2);

    gemm(n, 2 * CC, CC, s.H2, CC, 0, w.ffnW1, CC, 0, 1,
         s.FF1, 2 * CC, 0, 1, 1.0f, w.ffnB1, nullptr, 1, nullptr, nullptr);
    gemm(n, CC, 2 * CC, s.FF1, 2 * CC, 0, w.ffnW2, 2 * CC, 0, 1,
         outState, CC, 0, 1, 1.0f, w.ffnB2, nullptr, 0, s.H2, rowMask);
}

extern "C" void kernel_launch(void* const* d_in, const int* in_sizes, int n_in,
                              void* d_out, int out_size)
{
    const float* feats0  = (const float*)d_in[0];
    const float* feats1  = (const float*)d_in[1];
    const float* feats2  = (const float*)d_in[2];
    const float* nmask0  = (const float*)d_in[3];
    const float* nmask1  = (const float*)d_in[4];
    const float* nmask2  = (const float*)d_in[5];
    const int*   nbmask0 = (const int*)d_in[6];
    const int*   nbmask1 = (const int*)d_in[7];
    const float* emb_w   = (const float*)d_in[8];
    const float* emb_b   = (const float*)d_in[9];
    const float* sage_w  = (const float*)d_in[10];
    const float* sage_b  = (const float*)d_in[11];
    const float* qkv_w   = (const float*)d_in[12];
    const float* qkv_b   = (const float*)d_in[13];
    const float* out_w   = (const float*)d_in[14];
    const float* out_b   = (const float*)d_in[15];
    const float* n1_g    = (const float*)d_in[16];
    const float* n1_b    = (const float*)d_in[17];
    const float* n2_g    = (const float*)d_in[18];
    const float* n2_b    = (const float*)d_in[19];
    const float* ffn_w1  = (const float*)d_in[20];
    const float* ffn_b1  = (const float*)d_in[21];
    const float* ffn_w2  = (const float*)d_in[22];
    const float* ffn_b2  = (const float*)d_in[23];
    const float* cls_w   = (const float*)d_in[24];
    const float* cls_b   = (const float*)d_in[25];
    float* out = (float*)d_out;

    // allow >48KB dynamic smem for flash kernel (idempotent; capture-safe)
    cudaFuncSetAttribute(flash_kernel, cudaFuncAttributeMaxDynamicSharedMemorySize, FLASH_SMEM);

    Scratch s = get_scratch();

    LayerW w[NL];
    for (int li = 0; li < NL; li++) {
        w[li].sageW = sage_w + (long long)li * CC * 2 * CC;
        w[li].sageB = sage_b + li * CC;
        w[li].qkvW  = qkv_w  + (long long)li * 3 * CC * CC;
        w[li].qkvB  = qkv_b  + li * 3 * CC;
        w[li].outW  = out_w  + (long long)li * CC * CC;
        w[li].outB  = out_b  + li * CC;
        w[li].n1g   = n1_g + li * CC;  w[li].n1b = n1_b + li * CC;
        w[li].n2g   = n2_g + li * CC;  w[li].n2b = n2_b + li * CC;
        w[li].ffnW1 = ffn_w1 + (long long)li * 2 * CC * CC;
        w[li].ffnB1 = ffn_b1 + li * 2 * CC;
        w[li].ffnW2 = ffn_w2 + (long long)li * CC * 2 * CC;
        w[li].ffnB2 = ffn_b2 + li * CC;
    }

    // ---- embeddings (depth 0 and 1), masked ----
    gemm(N0, CC, INDIM, feats0, INDIM, 0, emb_w, INDIM, 0, 1,
         s.S0, CC, 0, 1, 1.0f, emb_b, nullptr, 0, nullptr, nmask0);
    gemm(N1, CC, INDIM, feats1, INDIM, 0, emb_w, INDIM, 0, 1,
         s.S1E, CC, 0, 1, 1.0f, emb_b, nullptr, 0, nullptr, nmask1);

    // ---- depth-2: aggregate RAW features, then one embedding GEMM ----
    agg_kernel<<<(int)(((long long)N1 * INDIM + 255) / 256), 256>>>(
        feats2, INDIM, nbmask1, nmask2, s.AGGF, s.AGGC, N1);
    gemm(N1, CC, INDIM, s.AGGF, INDIM, 0, emb_w, INDIM, 0, 1,
         s.AGG, CC, 0, 1, 1.0f, emb_b, s.AGGC, 0, nullptr, nullptr);

    // ---- layer 0, depth 1 (n = 4096) ----
    block_forward(N1, s.S1E, s.AGG, s.S1N, nmask1, w[0], s);

    // ---- layer 0, depth 0 ----
    agg_kernel<<<(int)(((long long)N0 * CC + 255) / 256), 256>>>(
        s.S1E, CC, nbmask0, nullptr, s.AGG, nullptr, N0);
    block_forward(N0, s.S0, s.AGG, s.S0, nmask0, w[0], s);

    // ---- layer 1, depth 0 ----
    agg_kernel<<<(int)(((long long)N0 * CC + 255) / 256), 256>>>(
        s.S1N, CC, nbmask0, nullptr, s.AGG, nullptr, N0);
    block_forward(N0, s.S0, s.AGG, s.S0, nmask0, w[1], s);

    // ---- classifier ----
    gemm(N0, NC, CC, s.S0, CC, 0, cls_w, CC, 0, 1,
         out, NC, 0, 1, 1.0f, cls_b, nullptr, 0, nullptr, nullptr);
}

// round 5
// speedup vs baseline: 3.0066x; 1.1914x over previous
#include <cuda_runtime.h>
#include <math.h>
#include <stdint.h>

// ---------------------------------------------------------------------------
// Problem constants
// ---------------------------------------------------------------------------
#define NL 2
#define HH 4
#define CC 512
#define INDIM 256
#define FAN 16
#define NC 47
#define DH 128
#define N0 256
#define N1 4096

// ---------------------------------------------------------------------------
// Device scratch
// ---------------------------------------------------------------------------
__device__ float g_S1E[N1 * CC];
__device__ float g_S1N[N1 * CC];
__device__ float g_S0[N0 * CC];
__device__ float g_AGGF[N1 * INDIM];
__device__ float g_AGGC[N1];
__device__ float g_AGG[N1 * CC];
__device__ float g_HL[N1 * CC];
__device__ float g_H1[N1 * CC];
__device__ float g_QKV[N1 * 3 * CC];
__device__ float g_ATTO[N1 * CC];
__device__ float g_ATT[N1 * CC];
__device__ float g_H2[N1 * CC];
__device__ float g_FF1[N1 * 2 * CC];

// ---------------------------------------------------------------------------
// tf32 / async helpers
// ---------------------------------------------------------------------------
__device__ __forceinline__ uint32_t f2tf32(float f) {
    uint32_t u;
    asm("cvt.rna.tf32.f32 %0, %1;" : "=r"(u) : "f"(f));
    return u;
}

__device__ __forceinline__ void mma_tf32(float* d, const uint32_t* a, const uint32_t* b,
                                         const float* c) {
    asm volatile(
        "mma.sync.aligned.m16n8k8.row.col.f32.tf32.tf32.f32 "
        "{%0,%1,%2,%3}, {%4,%5,%6,%7}, {%8,%9}, {%10,%11,%12,%13};\n"
        : "=f"(d[0]), "=f"(d[1]), "=f"(d[2]), "=f"(d[3])
        : "r"(a[0]), "r"(a[1]), "r"(a[2]), "r"(a[3]),
          "r"(b[0]), "r"(b[1]),
          "f"(c[0]), "f"(c[1]), "f"(c[2]), "f"(c[3]));
}

__device__ __forceinline__ void cpa16(float* smemDst, const float* gsrc, int srcBytes) {
    uint32_t saddr = (uint32_t)__cvta_generic_to_shared(smemDst);
    asm volatile("cp.async.cg.shared.global [%0], [%1], 16, %2;\n"
                 :: "r"(saddr), "l"(gsrc), "r"(srcBytes));
}
__device__ __forceinline__ void cpa_commit() {
    asm volatile("cp.async.commit_group;\n");
}
__device__ __forceinline__ void cpa_wait2() {
    asm volatile("cp.async.wait_group 2;\n");
}

// ---------------------------------------------------------------------------
// cp.async-pipelined tf32 GEMM:  C = alpha * [A | A2] x op(B) + epilogue
//   A rows [M], cols [K]; cols >= kSplit come from A2 (same lda). op(B):
//   transB ? B[N,K] : B[K,N]. 128x128x16 tiles, 4 stages, 2 CTAs/SM.
// ---------------------------------------------------------------------------
#define GBM 128
#define GBN 128
#define GBK 16
#define APITCH 20      // floats per A/BT row in smem
#define BPITCH 132     // floats per B (k-major) row
#define STAGES 4
#define STAGE_FLOATS (GBM * APITCH + GBM * APITCH)   // A (2560) + B-union (2560)
#define GEMM_SMEM (STAGES * STAGE_FLOATS * 4)

__global__ void __launch_bounds__(256, 2) gemm_tf32_kernel(
    int M, int N, int K,
    const float* __restrict__ A, int lda,
    const float* __restrict__ A2, int kSplit,
    const float* __restrict__ B, int ldb, int transB,
    float* __restrict__ C, int ldc,
    float alpha,
    const float* __restrict__ bias,
    const float* __restrict__ biasScale,
    int relu,
    const float* __restrict__ addC,
    const float* __restrict__ rowMask)
{
    extern __shared__ float sm[];

    const int bm = blockIdx.y * GBM;
    const int bn = blockIdx.x * GBN;
    const int t = threadIdx.x;
    const int lane = t & 31;
    const int wid = t >> 5;
    const int q = lane >> 2;
    const int r = lane & 3;
    const int wm = (wid & 1) * 64;
    const int wn = (wid >> 1) * 32;

    // load-index precompute
    const int am = t >> 2;            // A/BT row
    const int kg = (t & 3) << 2;      // k group (4 floats)
    const int bkr = t >> 5;           // B k row (non-trans)
    const int n4 = (t & 31) << 2;     // B col group (non-trans)

    float acc[4][4][4];
    #pragma unroll
    for (int mi = 0; mi < 4; mi++)
        #pragma unroll
        for (int ni = 0; ni < 4; ni++)
            #pragma unroll
            for (int e = 0; e < 4; e++) acc[mi][ni][e] = 0.0f;

    auto issueStage = [&](int buf, int k0) {
        float* sA = sm + buf * STAGE_FLOATS;
        float* sB = sA + GBM * APITCH;
        // ---- A (possibly split source) ----
        const float* Asrc = (k0 < kSplit) ? A : A2;
        const int kk = (k0 < kSplit) ? k0 : (k0 - kSplit);
        #pragma unroll
        for (int i = 0; i < 2; i++) {
            int gm = bm + am + 64 * i;
            int ok = (gm < M);
            const float* src = Asrc + (long long)(ok ? gm : 0) * lda + kk + kg;
            cpa16(sA + (am + 64 * i) * APITCH + kg, src, ok ? 16 : 0);
        }
        // ---- B ----
        if (transB) {
            #pragma unroll
            for (int i = 0; i < 2; i++) {
                int gn = bn + am + 64 * i;
                int ok = (gn < N);
                const float* src = B + (long long)(ok ? gn : 0) * ldb + k0 + kg;
                cpa16(sB + (am + 64 * i) * APITCH + kg, src, ok ? 16 : 0);
            }
        } else {
            #pragma unroll
            for (int i = 0; i < 2; i++) {
                int k = bkr + 8 * i;
                int gn = bn + n4;
                int rem = N - gn;
                int bytes = rem >= 4 ? 16 : (rem > 0 ? rem * 4 : 0);
                const float* src = B + (long long)(k0 + k) * ldb + (rem > 0 ? gn : 0);
                cpa16(sB + k * BPITCH + n4, src, bytes);
            }
        }
    };

    auto computeStage = [&](int buf) {
        const float* sA = sm + buf * STAGE_FLOATS;
        const float* sB = sA + GBM * APITCH;
        #pragma unroll
        for (int ks = 0; ks < 2; ks++) {
            const int kb = ks * 8;
            uint32_t af[4][4], bf[4][2];
            #pragma unroll
            for (int mi = 0; mi < 4; mi++) {
                int row0 = wm + mi * 16 + q;
                af[mi][0] = f2tf32(sA[row0 * APITCH + kb + r]);
                af[mi][1] = f2tf32(sA[(row0 + 8) * APITCH + kb + r]);
                af[mi][2] = f2tf32(sA[row0 * APITCH + kb + r + 4]);
                af[mi][3] = f2tf32(sA[(row0 + 8) * APITCH + kb + r + 4]);
            }
            if (transB) {
                #pragma unroll
                for (int ni = 0; ni < 4; ni++) {
                    int col = wn + ni * 8 + q;
                    bf[ni][0] = f2tf32(sB[col * APITCH + kb + r]);
                    bf[ni][1] = f2tf32(sB[col * APITCH + kb + r + 4]);
                }
            } else {
                #pragma unroll
                for (int ni = 0; ni < 4; ni++) {
                    int col = wn + ni * 8 + q;
                    bf[ni][0] = f2tf32(sB[(kb + r) * BPITCH + col]);
                    bf[ni][1] = f2tf32(sB[(kb + r + 4) * BPITCH + col]);
                }
            }
            #pragma unroll
            for (int mi = 0; mi < 4; mi++)
                #pragma unroll
                for (int ni = 0; ni < 4; ni++)
                    mma_tf32(acc[mi][ni], af[mi], bf[ni], acc[mi][ni]);
        }
    };

    const int ntiles = K / GBK;
    // prologue: stages 0..2 in flight (commit one group per stage, always)
    #pragma unroll
    for (int s = 0; s < STAGES - 1; s++) {
        if (s < ntiles) issueStage(s, s * GBK);
        cpa_commit();
    }
    for (int it = 0; it < ntiles; it++) {
        cpa_wait2();
        __syncthreads();
        const int nj = it + STAGES - 1;
        if (nj < ntiles) issueStage(nj & (STAGES - 1), nj * GBK);
        cpa_commit();
        computeStage(it & (STAGES - 1));
    }

    // ---- epilogue ----
    #pragma unroll
    for (int mi = 0; mi < 4; mi++) {
        #pragma unroll
        for (int ni = 0; ni < 4; ni++) {
            #pragma unroll
            for (int half = 0; half < 2; half++) {
                int gm = bm + wm + mi * 16 + q + half * 8;
                if (gm >= M) continue;
                float bs = biasScale ? biasScale[gm] : 1.0f;
                float rmv = rowMask ? rowMask[gm] : 1.0f;
                #pragma unroll
                for (int j = 0; j < 2; j++) {
                    int gn = bn + wn + ni * 8 + 2 * r + j;
                    if (gn >= N) continue;
                    float v = acc[mi][ni][half * 2 + j] * alpha;
                    if (bias) v += bias[gn] * bs;
                    if (relu) v = fmaxf(v, 0.0f);
                    if (addC) v += addC[(long long)gm * ldc + gn];
                    v *= rmv;
                    C[(long long)gm * ldc + gn] = v;
                }
            }
        }
    }
}

// ---------------------------------------------------------------------------
// Flash attention (tf32 mma, online softmax). Q held in registers (pre-scaled).
// One CTA = 64 query rows x 1 head, 128 threads / 4 warps. KV tiles of 64.
// ---------------------------------------------------------------------------
#define FTM 64
#define FTN 64
#define FPITCH 132
#define PPITCH 68
#define FLASH_SMEM ((2 * FTN * FPITCH + FTM * PPITCH) * 4)

__global__ void __launch_bounds__(128) flash_kernel(
    const float* __restrict__ QKV, float* __restrict__ O, int n)
{
    extern __shared__ float fsm[];
    float* sK = fsm;
    float* sV = sK + FTN * FPITCH;
    uint32_t* uK = (uint32_t*)sK;
    uint32_t* uV = (uint32_t*)sV;
    uint32_t* uP = (uint32_t*)(sV + FTN * FPITCH);

    const int t = threadIdx.x;
    const int warp = t >> 5;
    const int lane = t & 31;
    const int q = lane >> 2;
    const int r = lane & 3;
    const int head = blockIdx.y;
    const int qbase = blockIdx.x * FTM;
    const int row0 = warp * 16 + q;

    const float scale = 0.08838834764831845f;  // 1/sqrt(128)

    // ---- Q fragments in registers, pre-scaled ----
    uint32_t qf[16][4];
    {
        const float* q0 = QKV + (long long)(qbase + row0) * (3 * CC) + head * DH;
        const float* q1 = QKV + (long long)(qbase + row0 + 8) * (3 * CC) + head * DH;
        #pragma unroll
        for (int kc = 0; kc < 16; kc++) {
            qf[kc][0] = f2tf32(q0[kc * 8 + r] * scale);
            qf[kc][1] = f2tf32(q1[kc * 8 + r] * scale);
            qf[kc][2] = f2tf32(q0[kc * 8 + r + 4] * scale);
            qf[kc][3] = f2tf32(q1[kc * 8 + r + 4] * scale);
        }
    }

    float oacc[16][4];
    #pragma unroll
    for (int df = 0; df < 16; df++)
        #pragma unroll
        for (int e = 0; e < 4; e++) oacc[df][e] = 0.0f;
    float m0 = -1e30f, m1 = -1e30f, l0 = 0.0f, l1 = 0.0f;

    const int ntiles = n / FTN;
    for (int kt = 0; kt < ntiles; kt++) {
        __syncthreads();
        // ---- load K, V tiles ----
        #pragma unroll
        for (int i = 0; i < 16; i++) {
            int idx = t + i * 128;
            int row = idx >> 5;
            int c4 = idx & 31;
            long long gro = (long long)(kt * FTN + row) * (3 * CC) + head * DH + c4 * 4;
            const float4 kv = *reinterpret_cast<const float4*>(QKV + gro + CC);
            uint32_t* dk = uK + row * FPITCH + c4 * 4;
            dk[0] = f2tf32(kv.x); dk[1] = f2tf32(kv.y); dk[2] = f2tf32(kv.z); dk[3] = f2tf32(kv.w);
            const float4 vv = *reinterpret_cast<const float4*>(QKV + gro + 2 * CC);
            uint32_t* dv = uV + row * FPITCH + c4 * 4;
            dv[0] = f2tf32(vv.x); dv[1] = f2tf32(vv.y); dv[2] = f2tf32(vv.z); dv[3] = f2tf32(vv.w);
        }
        __syncthreads();

        // ---- S = Qs @ K^T (Q pre-scaled) ----
        float sacc[8][4];
        #pragma unroll
        for (int nf = 0; nf < 8; nf++)
            #pragma unroll
            for (int e = 0; e < 4; e++) sacc[nf][e] = 0.0f;
        #pragma unroll
        for (int kc = 0; kc < 16; kc++) {
            const int kb = kc * 8;
            #pragma unroll
            for (int nf = 0; nf < 8; nf++) {
                const int col = nf * 8 + q;
                uint32_t bf[2];
                bf[0] = uK[col * FPITCH + kb + r];
                bf[1] = uK[col * FPITCH + kb + r + 4];
                mma_tf32(sacc[nf], qf[kc], bf, sacc[nf]);
            }
        }

        // ---- online softmax ----
        float tm0 = -1e30f, tm1 = -1e30f;
        #pragma unroll
        for (int nf = 0; nf < 8; nf++) {
            tm0 = fmaxf(tm0, fmaxf(sacc[nf][0], sacc[nf][1]));
            tm1 = fmaxf(tm1, fmaxf(sacc[nf][2], sacc[nf][3]));
        }
        tm0 = fmaxf(tm0, __shfl_xor_sync(0xffffffffu, tm0, 1));
        tm0 = fmaxf(tm0, __shfl_xor_sync(0xffffffffu, tm0, 2));
        tm1 = fmaxf(tm1, __shfl_xor_sync(0xffffffffu, tm1, 1));
        tm1 = fmaxf(tm1, __shfl_xor_sync(0xffffffffu, tm1, 2));
        const float nm0 = fmaxf(m0, tm0);
        const float nm1 = fmaxf(m1, tm1);
        const float cor0 = __expf(m0 - nm0);
        const float cor1 = __expf(m1 - nm1);
        m0 = nm0; m1 = nm1;

        float ts0 = 0.0f, ts1 = 0.0f;
        #pragma unroll
        for (int nf = 0; nf < 8; nf++) {
            const float p0 = __expf(sacc[nf][0] - m0);
            const float p1 = __expf(sacc[nf][1] - m0);
            const float p2 = __expf(sacc[nf][2] - m1);
            const float p3 = __expf(sacc[nf][3] - m1);
            ts0 += p0 + p1;
            ts1 += p2 + p3;
            const int colb = nf * 8 + 2 * r;
            uP[row0 * PPITCH + colb]           = f2tf32(p0);
            uP[row0 * PPITCH + colb + 1]       = f2tf32(p1);
            uP[(row0 + 8) * PPITCH + colb]     = f2tf32(p2);
            uP[(row0 + 8) * PPITCH + colb + 1] = f2tf32(p3);
        }
        ts0 += __shfl_xor_sync(0xffffffffu, ts0, 1);
        ts0 += __shfl_xor_sync(0xffffffffu, ts0, 2);
        ts1 += __shfl_xor_sync(0xffffffffu, ts1, 1);
        ts1 += __shfl_xor_sync(0xffffffffu, ts1, 2);
        l0 = l0 * cor0 + ts0;
        l1 = l1 * cor1 + ts1;

        #pragma unroll
        for (int df = 0; df < 16; df++) {
            oacc[df][0] *= cor0; oacc[df][1] *= cor0;
            oacc[df][2] *= cor1; oacc[df][3] *= cor1;
        }
        __syncwarp();

        // ---- O += P @ V ----
        #pragma unroll
        for (int kc = 0; kc < 8; kc++) {
            const int kb = kc * 8;
            uint32_t af[4];
            af[0] = uP[row0 * PPITCH + kb + r];
            af[1] = uP[(row0 + 8) * PPITCH + kb + r];
            af[2] = uP[row0 * PPITCH + kb + r + 4];
            af[3] = uP[(row0 + 8) * PPITCH + kb + r + 4];
            #pragma unroll
            for (int df = 0; df < 16; df++) {
                uint32_t bf[2];
                bf[0] = uV[(kb + r) * FPITCH + df * 8 + q];
                bf[1] = uV[(kb + r + 4) * FPITCH + df * 8 + q];
                mma_tf32(oacc[df], af, bf, oacc[df]);
            }
        }
    }

    // ---- epilogue ----
    const float inv0 = 1.0f / l0;
    const float inv1 = 1.0f / l1;
    #pragma unroll
    for (int df = 0; df < 16; df++) {
        const int gc = head * DH + df * 8 + 2 * r;
        O[(long long)(qbase + row0) * CC + gc]         = oacc[df][0] * inv0;
        O[(long long)(qbase + row0) * CC + gc + 1]     = oacc[df][1] * inv0;
        O[(long long)(qbase + row0 + 8) * CC + gc]     = oacc[df][2] * inv1;
        O[(long long)(qbase + row0 + 8) * CC + gc + 1] = oacc[df][3] * inv1;
    }
}

// ---------------------------------------------------------------------------
// Block reduction (sum)
// ---------------------------------------------------------------------------
__device__ __forceinline__ float blockReduceSum(float v, float* red) {
    #pragma unroll
    for (int o = 16; o > 0; o >>= 1) v += __shfl_xor_sync(0xffffffffu, v, o);
    int w = threadIdx.x >> 5;
    if ((threadIdx.x & 31) == 0) red[w] = v;
    __syncthreads();
    float r;
    if (threadIdx.x < 32) {
        r = (threadIdx.x < (blockDim.x >> 5)) ? red[threadIdx.x] : 0.0f;
        #pragma unroll
        for (int o = 16; o > 0; o >>= 1) r += __shfl_xor_sync(0xffffffffu, r, o);
        if (threadIdx.x == 0) red[0] = r;
    }
    __syncthreads();
    r = red[0];
    __syncthreads();
    return r;
}

// ---------------------------------------------------------------------------
// out[row] = LN(a[row] + b[row]) * g + beta
// ---------------------------------------------------------------------------
__global__ void add_ln_kernel(const float* __restrict__ a, const float* __restrict__ b,
                              const float* __restrict__ g, const float* __restrict__ be,
                              float* __restrict__ out)
{
    long long row = blockIdx.x;
    const float* ar = a + row * CC;
    const float* br = b + row * CC;
    int tid = threadIdx.x;
    float x0 = ar[tid] + br[tid];
    float x1 = ar[tid + 256] + br[tid + 256];
    __shared__ float red[8];
    float mu = blockReduceSum(x0 + x1, red) * (1.0f / CC);
    float d0 = x0 - mu, d1 = x1 - mu;
    float var = blockReduceSum(d0 * d0 + d1 * d1, red) * (1.0f / CC);
    float rstd = rsqrtf(var + 1e-5f);
    out[row * CC + tid]       = d0 * rstd * g[tid] + be[tid];
    out[row * CC + tid + 256] = d1 * rstd * g[tid + 256] + be[tid + 256];
}

// ---------------------------------------------------------------------------
// Masked-mean neighbor aggregation
// ---------------------------------------------------------------------------
__global__ void agg_kernel(const float* __restrict__ X, int C,
                           const int* __restrict__ nbm,
                           const float* __restrict__ childMask,
                           float* __restrict__ out, float* __restrict__ coefOut, int P)
{
    long long idx = (long long)blockIdx.x * blockDim.x + threadIdx.x;
    if (idx >= (long long)P * C) return;
    int p = (int)(idx / C);
    int c = (int)(idx % C);
    float sum = 0.0f, den = 0.0f, wsum = 0.0f;
    #pragma unroll
    for (int f = 0; f < FAN; f++) {
        float nb = (float)nbm[p * FAN + f];
        den += nb;
        float w = nb * (childMask ? childMask[p * FAN + f] : 1.0f);
        wsum += w;
        sum += w * X[(long long)(p * FAN + f) * C + c];
    }
    den = fmaxf(den, 1.0f);
    out[(long long)p * C + c] = sum / den;
    if (coefOut && c == 0) coefOut[p] = wsum / den;
}

// ---------------------------------------------------------------------------
// Host-side orchestration
// ---------------------------------------------------------------------------
static void gemm(int M, int N, int K,
                 const float* A, int lda, const float* A2, int kSplit,
                 const float* B, int ldb, int transB,
                 float* C, int ldc,
                 float alpha, const float* bias, const float* biasScale, int relu,
                 const float* addC, const float* rowMask)
{
    dim3 grid((N + GBN - 1) / GBN, (M + GBM - 1) / GBM);
    gemm_tf32_kernel<<<grid, 256, GEMM_SMEM>>>(
        M, N, K, A, lda, A2, kSplit, B, ldb, transB, C, ldc,
        alpha, bias, biasScale, relu, addC, rowMask);
}

struct Scratch {
    float *S1E, *S1N, *S0, *AGGF, *AGGC, *AGG, *HL, *H1, *QKV, *ATTO, *ATT, *H2, *FF1;
};

static Scratch get_scratch() {
    Scratch s;
    void* p;
    cudaGetSymbolAddress(&p, g_S1E);  s.S1E  = (float*)p;
    cudaGetSymbolAddress(&p, g_S1N);  s.S1N  = (float*)p;
    cudaGetSymbolAddress(&p, g_S0);   s.S0   = (float*)p;
    cudaGetSymbolAddress(&p, g_AGGF); s.AGGF = (float*)p;
    cudaGetSymbolAddress(&p, g_AGGC); s.AGGC = (float*)p;
    cudaGetSymbolAddress(&p, g_AGG);  s.AGG  = (float*)p;
    cudaGetSymbolAddress(&p, g_HL);   s.HL   = (float*)p;
    cudaGetSymbolAddress(&p, g_H1);   s.H1   = (float*)p;
    cudaGetSymbolAddress(&p, g_QKV);  s.QKV  = (float*)p;
    cudaGetSymbolAddress(&p, g_ATTO); s.ATTO = (float*)p;
    cudaGetSymbolAddress(&p, g_ATT);  s.ATT  = (float*)p;
    cudaGetSymbolAddress(&p, g_H2);   s.H2   = (float*)p;
    cudaGetSymbolAddress(&p, g_FF1);  s.FF1  = (float*)p;
    return s;
}

struct LayerW {
    const float *sageW, *sageB, *qkvW, *qkvB, *outW, *outB;
    const float *n1g, *n1b, *n2g, *n2b, *ffnW1, *ffnB1, *ffnW2, *ffnB2;
};

static void block_forward(int n, const float* sf, const float* agg, float* outState,
                          const float* rowMask, const LayerW& w, const Scratch& s)
{
    // GraphSAGE: [sf | agg] @ sageW^T  (concat fused via split-A)
    gemm(n, CC, 2 * CC, sf, CC, agg, CC, w.sageW, 2 * CC, 1,
         s.HL, CC, 1.0f, w.sageB, nullptr, 0, nullptr, nullptr);
    add_ln_kernel<<<n, 256>>>(sf, s.HL, w.n1g, w.n1b, s.H1);

    gemm(n, 3 * CC, CC, s.H1, CC, nullptr, CC, w.qkvW, CC, 1,
         s.QKV, 3 * CC, 1.0f, w.qkvB, nullptr, 0, nullptr, nullptr);

    {
        dim3 grid(n / FTM, HH);
        flash_kernel<<<grid, 128, FLASH_SMEM>>>(s.QKV, s.ATTO, n);
    }

    gemm(n, CC, CC, s.ATTO, CC, nullptr, CC, w.outW, CC, 1,
         s.ATT, CC, 1.0f, w.outB, nullptr, 0, nullptr, nullptr);
    add_ln_kernel<<<n, 256>>>(s.H1, s.ATT, w.n2g, w.n2b, s.H2);

    gemm(n, 2 * CC, CC, s.H2, CC, nullptr, CC, w.ffnW1, CC, 1,
         s.FF1, 2 * CC, 1.0f, w.ffnB1, nullptr, 1, nullptr, nullptr);
    gemm(n, CC, 2 * CC, s.FF1, 2 * CC, nullptr, 2 * CC, w.ffnW2, 2 * CC, 1,
         outState, CC, 1.0f, w.ffnB2, nullptr, 0, s.H2, rowMask);
}

extern "C" void kernel_launch(void* const* d_in, const int* in_sizes, int n_in,
                              void* d_out, int out_size)
{
    const float* feats0  = (const float*)d_in[0];
    const float* feats1  = (const float*)d_in[1];
    const float* feats2  = (const float*)d_in[2];
    const float* nmask0  = (const float*)d_in[3];
    const float* nmask1  = (const float*)d_in[4];
    const float* nmask2  = (const float*)d_in[5];
    const int*   nbmask0 = (const int*)d_in[6];
    const int*   nbmask1 = (const int*)d_in[7];
    const float* emb_w   = (const float*)d_in[8];
    const float* emb_b   = (const float*)d_in[9];
    const float* sage_w  = (const float*)d_in[10];
    const float* sage_b  = (const float*)d_in[11];
    const float* qkv_w   = (const float*)d_in[12];
    const float* qkv_b   = (const float*)d_in[13];
    const float* out_w   = (const float*)d_in[14];
    const float* out_b   = (const float*)d_in[15];
    const float* n1_g    = (const float*)d_in[16];
    const float* n1_b    = (const float*)d_in[17];
    const float* n2_g    = (const float*)d_in[18];
    const float* n2_b    = (const float*)d_in[19];
    const float* ffn_w1  = (const float*)d_in[20];
    const float* ffn_b1  = (const float*)d_in[21];
    const float* ffn_w2  = (const float*)d_in[22];
    const float* ffn_b2  = (const float*)d_in[23];
    const float* cls_w   = (const float*)d_in[24];
    const float* cls_b   = (const float*)d_in[25];
    float* out = (float*)d_out;

    cudaFuncSetAttribute(flash_kernel, cudaFuncAttributeMaxDynamicSharedMemorySize, FLASH_SMEM);
    cudaFuncSetAttribute(gemm_tf32_kernel, cudaFuncAttributeMaxDynamicSharedMemorySize, GEMM_SMEM);

    Scratch s = get_scratch();

    LayerW w[NL];
    for (int li = 0; li < NL; li++) {
        w[li].sageW = sage_w + (long long)li * CC * 2 * CC;
        w[li].sageB = sage_b + li * CC;
        w[li].qkvW  = qkv_w  + (long long)li * 3 * CC * CC;
        w[li].qkvB  = qkv_b  + li * 3 * CC;
        w[li].outW  = out_w  + (long long)li * CC * CC;
        w[li].outB  = out_b  + li * CC;
        w[li].n1g   = n1_g + li * CC;  w[li].n1b = n1_b + li * CC;
        w[li].n2g   = n2_g + li * CC;  w[li].n2b = n2_b + li * CC;
        w[li].ffnW1 = ffn_w1 + (long long)li * 2 * CC * CC;
        w[li].ffnB1 = ffn_b1 + li * 2 * CC;
        w[li].ffnW2 = ffn_w2 + (long long)li * CC * 2 * CC;
        w[li].ffnB2 = ffn_b2 + li * CC;
    }

    // ---- embeddings (depth 0 and 1), masked ----
    gemm(N0, CC, INDIM, feats0, INDIM, nullptr, INDIM, emb_w, INDIM, 1,
         s.S0, CC, 1.0f, emb_b, nullptr, 0, nullptr, nmask0);
    gemm(N1, CC, INDIM, feats1, INDIM, nullptr, INDIM, emb_w, INDIM, 1,
         s.S1E, CC, 1.0f, emb_b, nullptr, 0, nullptr, nmask1);

    // ---- depth-2: aggregate RAW features, then one embedding GEMM ----
    agg_kernel<<<(int)(((long long)N1 * INDIM + 255) / 256), 256>>>(
        feats2, INDIM, nbmask1, nmask2, s.AGGF, s.AGGC, N1);
    gemm(N1, CC, INDIM, s.AGGF, INDIM, nullptr, INDIM, emb_w, INDIM, 1,
         s.AGG, CC, 1.0f, emb_b, s.AGGC, 0, nullptr, nullptr);

    // ---- layer 0, depth 1 (n = 4096) ----
    block_forward(N1, s.S1E, s.AGG, s.S1N, nmask1, w[0], s);

    // ---- layer 0, depth 0 ----
    agg_kernel<<<(int)(((long long)N0 * CC + 255) / 256), 256>>>(
        s.S1E, CC, nbmask0, nullptr, s.AGG, nullptr, N0);
    block_forward(N0, s.S0, s.AGG, s.S0, nmask0, w[0], s);

    // ---- layer 1, depth 0 ----
    agg_kernel<<<(int)(((long long)N0 * CC + 255) / 256), 256>>>(
        s.S1N, CC, nbmask0, nullptr, s.AGG, nullptr, N0);
    block_forward(N0, s.S0, s.AGG, s.S0, nmask0, w[1], s);

    // ---- classifier ----
    gemm(N0, NC, CC, s.S0, CC, nullptr, CC, cls_w, CC, 1,
         out, NC, 1.0f, cls_b, nullptr, 0, nullptr, nullptr);
}

// round 6
// speedup vs baseline: 6.8962x; 2.2937x over previous
#include <cuda_runtime.h>
#include <cuda_fp16.h>
#include <math.h>
#include <stdint.h>

// ---------------------------------------------------------------------------
// Problem constants
// ---------------------------------------------------------------------------
#define NL 2
#define HH 4
#define CC 512
#define INDIM 256
#define FAN 16
#define NC 47
#define DH 128
#define N0 256
#define N1 4096

// ---------------------------------------------------------------------------
// Device scratch (fp32 + half mirrors)
// ---------------------------------------------------------------------------
__device__ float g_S1E[N1 * CC];
__device__ float g_S1N[N1 * CC];
__device__ float g_S0[N0 * CC];
__device__ float g_AGGC[N1];
__device__ float g_HL[N1 * CC];
__device__ float g_H1[N1 * CC];
__device__ float g_ATT[N1 * CC];
__device__ float g_H2[N1 * CC];

__device__ __half g_S1Eh[N1 * CC];
__device__ __half g_S0h[N0 * CC];
__device__ __half g_AGGFh[N1 * INDIM];
__device__ __half g_AGGh[N1 * CC];
__device__ __half g_H1h[N1 * CC];
__device__ __half g_QKVh[N1 * 3 * CC];
__device__ __half g_ATTOh[N1 * CC];
__device__ __half g_H2h[N1 * CC];
__device__ __half g_FF1h[N1 * 2 * CC];

// half weights
__device__ __half g_embWh[CC * INDIM];
__device__ __half g_sageWh[NL * CC * 2 * CC];
__device__ __half g_qkvWh[NL * 3 * CC * CC];
__device__ __half g_outWh[NL * CC * CC];
__device__ __half g_ffnW1h[NL * 2 * CC * CC];
__device__ __half g_ffnW2h[NL * CC * 2 * CC];
__device__ __half g_clsWh[NC * CC];
__device__ __half g_feats0h[N0 * INDIM];
__device__ __half g_feats1h[N1 * INDIM];

// ---------------------------------------------------------------------------
// helpers
// ---------------------------------------------------------------------------
__device__ __forceinline__ void mma_f16(float* d, const uint32_t* a, const uint32_t* b,
                                        const float* c) {
    asm volatile(
        "mma.sync.aligned.m16n8k16.row.col.f32.f16.f16.f32 "
        "{%0,%1,%2,%3}, {%4,%5,%6,%7}, {%8,%9}, {%10,%11,%12,%13};\n"
        : "=f"(d[0]), "=f"(d[1]), "=f"(d[2]), "=f"(d[3])
        : "r"(a[0]), "r"(a[1]), "r"(a[2]), "r"(a[3]),
          "r"(b[0]), "r"(b[1]),
          "f"(c[0]), "f"(c[1]), "f"(c[2]), "f"(c[3]));
}

__device__ __forceinline__ void ldsm_x4(uint32_t& r0, uint32_t& r1, uint32_t& r2,
                                        uint32_t& r3, uint32_t addr) {
    asm volatile("ldmatrix.sync.aligned.m8n8.x4.shared.b16 {%0,%1,%2,%3}, [%4];"
                 : "=r"(r0), "=r"(r1), "=r"(r2), "=r"(r3) : "r"(addr));
}
__device__ __forceinline__ void ldsm_x4_t(uint32_t& r0, uint32_t& r1, uint32_t& r2,
                                          uint32_t& r3, uint32_t addr) {
    asm volatile("ldmatrix.sync.aligned.m8n8.x4.trans.shared.b16 {%0,%1,%2,%3}, [%4];"
                 : "=r"(r0), "=r"(r1), "=r"(r2), "=r"(r3) : "r"(addr));
}

__device__ __forceinline__ void cpa16(void* smemDst, const void* gsrc, int srcBytes) {
    uint32_t saddr = (uint32_t)__cvta_generic_to_shared(smemDst);
    asm volatile("cp.async.cg.shared.global [%0], [%1], 16, %2;\n"
                 :: "r"(saddr), "l"(gsrc), "r"(srcBytes));
}
__device__ __forceinline__ void cpa_commit() { asm volatile("cp.async.commit_group;\n"); }
__device__ __forceinline__ void cpa_wait2() { asm volatile("cp.async.wait_group 2;\n"); }
__device__ __forceinline__ void cpa_wait0() { asm volatile("cp.async.wait_group 0;\n"); }

__device__ __forceinline__ uint32_t scale_h2(uint32_t u, float s) {
    __half2 hv = *reinterpret_cast<const __half2*>(&u);
    float2 f = __half22float2(hv);
    __half2 o = __floats2half2_rn(f.x * s, f.y * s);
    return *reinterpret_cast<uint32_t*>(&o);
}
__device__ __forceinline__ uint32_t pack_h2(float a, float b) {
    __half2 o = __floats2half2_rn(a, b);
    return *reinterpret_cast<uint32_t*>(&o);
}

// ---------------------------------------------------------------------------
// fp16 cp.async GEMM: C = [A | A2](half) x B^T(half) + epilogue
//   A: [M,K] half (cols >= kSplit from A2); B: [N,K] half row-major.
//   Tiles 128x64x32, 4 stages, 256 thr (8 warps of 32x32), 2 CTAs/SM.
// ---------------------------------------------------------------------------
#define GBM 128
#define GBN 64
#define KT 32
#define APH 40                         // halves per smem row (20 b32)
#define STAGE_H ((GBM + GBN) * APH)    // 7680 halves
#define STAGES 4
#define GEMM_SMEM (STAGES * STAGE_H * 2)

__global__ void __launch_bounds__(256, 2) gemm_f16_kernel(
    int M, int N, int K,
    const __half* __restrict__ A, int lda,
    const __half* __restrict__ A2, int kSplit,
    const __half* __restrict__ B, int ldb,
    float* __restrict__ C, __half* __restrict__ Ch, int ldc,
    const float* __restrict__ bias,
    const float* __restrict__ biasScale,
    int relu,
    const float* __restrict__ addC,
    const float* __restrict__ rowMask)
{
    extern __shared__ __half smh[];

    const int bm = blockIdx.y * GBM;
    const int bn = blockIdx.x * GBN;
    const int t = threadIdx.x;
    const int lane = t & 31;
    const int wid = t >> 5;
    const int q = lane >> 2;
    const int r = lane & 3;
    const int wm = (wid & 3) * 32;
    const int wn = (wid >> 2) * 32;

    float acc[2][4][4];
    #pragma unroll
    for (int mi = 0; mi < 2; mi++)
        #pragma unroll
        for (int ni = 0; ni < 4; ni++)
            #pragma unroll
            for (int e = 0; e < 4; e++) acc[mi][ni][e] = 0.0f;

    auto issueStage = [&](int buf, int k0) {
        __half* sA = smh + buf * STAGE_H;
        __half* sB = sA + GBM * APH;
        const __half* Asrc = (k0 < kSplit) ? A : A2;
        const int kk = (k0 < kSplit) ? k0 : (k0 - kSplit);
        #pragma unroll
        for (int i = 0; i < 2; i++) {
            int idx = t + 256 * i;
            int row = idx >> 2;
            int c8 = (idx & 3) * 8;
            int gm = bm + row;
            int ok = (gm < M);
            cpa16(sA + row * APH + c8,
                  Asrc + (long long)(ok ? gm : 0) * lda + kk + c8, ok ? 16 : 0);
        }
        {
            int row = t >> 2;
            int c8 = (t & 3) * 8;
            int gn = bn + row;
            int ok = (gn < N);
            cpa16(sB + row * APH + c8,
                  B + (long long)(ok ? gn : 0) * ldb + k0 + c8, ok ? 16 : 0);
        }
    };

    auto computeStage = [&](int buf) {
        const uint32_t* sA32 = (const uint32_t*)(smh + buf * STAGE_H);
        const uint32_t* sB32 = (const uint32_t*)(smh + buf * STAGE_H + GBM * APH);
        #pragma unroll
        for (int ks = 0; ks < 2; ks++) {
            uint32_t af[2][4], bf[4][2];
            #pragma unroll
            for (int mi = 0; mi < 2; mi++) {
                int row0 = wm + mi * 16 + q;
                af[mi][0] = sA32[row0 * 20 + ks * 8 + r];
                af[mi][1] = sA32[(row0 + 8) * 20 + ks * 8 + r];
                af[mi][2] = sA32[row0 * 20 + ks * 8 + r + 4];
                af[mi][3] = sA32[(row0 + 8) * 20 + ks * 8 + r + 4];
            }
            #pragma unroll
            for (int ni = 0; ni < 4; ni++) {
                int col = wn + ni * 8 + q;
                bf[ni][0] = sB32[col * 20 + ks * 8 + r];
                bf[ni][1] = sB32[col * 20 + ks * 8 + r + 4];
            }
            #pragma unroll
            for (int mi = 0; mi < 2; mi++)
                #pragma unroll
                for (int ni = 0; ni < 4; ni++)
                    mma_f16(acc[mi][ni], af[mi], bf[ni], acc[mi][ni]);
        }
    };

    const int ntiles = K / KT;
    #pragma unroll
    for (int s = 0; s < STAGES - 1; s++) {
        if (s < ntiles) issueStage(s, s * KT);
        cpa_commit();
    }
    for (int it = 0; it < ntiles; it++) {
        cpa_wait2();
        __syncthreads();
        const int nj = it + STAGES - 1;
        if (nj < ntiles) issueStage(nj & (STAGES - 1), nj * KT);
        cpa_commit();
        computeStage(it & (STAGES - 1));
    }

    // ---- epilogue ----
    #pragma unroll
    for (int mi = 0; mi < 2; mi++) {
        #pragma unroll
        for (int hh = 0; hh < 2; hh++) {
            int gm = bm + wm + mi * 16 + q + hh * 8;
            if (gm >= M) continue;
            float bs = biasScale ? biasScale[gm] : 1.0f;
            float rmv = rowMask ? rowMask[gm] : 1.0f;
            #pragma unroll
            for (int ni = 0; ni < 4; ni++) {
                float v[2];
                #pragma unroll
                for (int j = 0; j < 2; j++) {
                    int gn = bn + wn + ni * 8 + 2 * r + j;
                    float x = acc[mi][ni][hh * 2 + j];
                    if (bias) x += bias[gn] * bs;
                    if (relu) x = fmaxf(x, 0.0f);
                    if (addC) x += addC[(long long)gm * ldc + gn];
                    v[j] = x * rmv;
                }
                int gn0 = bn + wn + ni * 8 + 2 * r;
                if (gn0 >= N) continue;
                if (C) {
                    C[(long long)gm * ldc + gn0] = v[0];
                    if (gn0 + 1 < N) C[(long long)gm * ldc + gn0 + 1] = v[1];
                }
                if (Ch) {
                    *reinterpret_cast<__half2*>(Ch + (long long)gm * ldc + gn0) =
                        __floats2half2_rn(v[0], v[1]);
                }
            }
        }
    }
}

// ---------------------------------------------------------------------------
// fp16 flash attention: Q+P in registers, K/V via ldmatrix, online softmax.
// CTA = 64 query rows x 1 head, 128 thr / 4 warps; KV tiles of 64.
// ---------------------------------------------------------------------------
#define FPITCH_H 136

__global__ void __launch_bounds__(128) flash_f16_kernel(
    const __half* __restrict__ QKV, __half* __restrict__ O, int n)
{
    __shared__ __half sK[64 * FPITCH_H];
    __shared__ __half sV[64 * FPITCH_H];

    const int t = threadIdx.x;
    const int warp = t >> 5;
    const int lane = t & 31;
    const int q = lane >> 2;
    const int r = lane & 3;
    const int head = blockIdx.y;
    const int qbase = blockIdx.x * 64;
    const int row0 = warp * 16 + q;
    const float scale = 0.08838834764831845f;  // 1/sqrt(128)

    const uint32_t skb = (uint32_t)__cvta_generic_to_shared(sK);
    const uint32_t svb = (uint32_t)__cvta_generic_to_shared(sV);

    // ---- Q fragments in regs, pre-scaled ----
    uint32_t qf[8][4];
    {
        const __half* q0p = QKV + (long long)(qbase + row0) * (3 * CC) + head * DH;
        const __half* q1p = q0p + 8LL * (3 * CC);
        #pragma unroll
        for (int kc = 0; kc < 8; kc++) {
            qf[kc][0] = scale_h2(*(const uint32_t*)(q0p + kc * 16 + 2 * r), scale);
            qf[kc][1] = scale_h2(*(const uint32_t*)(q1p + kc * 16 + 2 * r), scale);
            qf[kc][2] = scale_h2(*(const uint32_t*)(q0p + kc * 16 + 2 * r + 8), scale);
            qf[kc][3] = scale_h2(*(const uint32_t*)(q1p + kc * 16 + 2 * r + 8), scale);
        }
    }

    float oacc[16][4];
    #pragma unroll
    for (int df = 0; df < 16; df++)
        #pragma unroll
        for (int e = 0; e < 4; e++) oacc[df][e] = 0.0f;
    float m0 = -1e30f, m1 = -1e30f, l0 = 0.0f, l1 = 0.0f;

    const int grp = lane >> 3;
    const int lr = lane & 7;

    const int ntiles = n / 64;
    for (int kt = 0; kt < ntiles; kt++) {
        __syncthreads();
        #pragma unroll
        for (int i = 0; i < 8; i++) {
            int idx = t + 128 * i;
            int row = idx >> 4;
            int c8 = (idx & 15) * 8;
            const __half* kp = QKV + (long long)(kt * 64 + row) * (3 * CC) + CC + head * DH + c8;
            cpa16(sK + row * FPITCH_H + c8, kp, 16);
            cpa16(sV + row * FPITCH_H + c8, kp + CC, 16);
        }
        cpa_commit();
        cpa_wait0();
        __syncthreads();

        // ---- S = Qs @ K^T ----
        float sacc[8][4];
        #pragma unroll
        for (int nf = 0; nf < 8; nf++)
            #pragma unroll
            for (int e = 0; e < 4; e++) sacc[nf][e] = 0.0f;
        #pragma unroll
        for (int kc = 0; kc < 8; kc++) {
            #pragma unroll
            for (int nfp = 0; nfp < 4; nfp++) {
                int kvr = nfp * 16 + ((grp & 2) ? 8 : 0) + lr;
                int dc = kc * 16 + ((grp & 1) ? 8 : 0);
                uint32_t b0, b1, b2, b3;
                ldsm_x4(b0, b1, b2, b3, skb + (kvr * FPITCH_H + dc) * 2);
                uint32_t bA[2] = {b0, b1}, bB[2] = {b2, b3};
                mma_f16(sacc[2 * nfp], qf[kc], bA, sacc[2 * nfp]);
                mma_f16(sacc[2 * nfp + 1], qf[kc], bB, sacc[2 * nfp + 1]);
            }
        }

        // ---- online softmax ----
        float tm0 = -1e30f, tm1 = -1e30f;
        #pragma unroll
        for (int nf = 0; nf < 8; nf++) {
            tm0 = fmaxf(tm0, fmaxf(sacc[nf][0], sacc[nf][1]));
            tm1 = fmaxf(tm1, fmaxf(sacc[nf][2], sacc[nf][3]));
        }
        tm0 = fmaxf(tm0, __shfl_xor_sync(0xffffffffu, tm0, 1));
        tm0 = fmaxf(tm0, __shfl_xor_sync(0xffffffffu, tm0, 2));
        tm1 = fmaxf(tm1, __shfl_xor_sync(0xffffffffu, tm1, 1));
        tm1 = fmaxf(tm1, __shfl_xor_sync(0xffffffffu, tm1, 2));
        const float nm0 = fmaxf(m0, tm0);
        const float nm1 = fmaxf(m1, tm1);
        const float cor0 = __expf(m0 - nm0);
        const float cor1 = __expf(m1 - nm1);
        m0 = nm0; m1 = nm1;

        float ts0 = 0.0f, ts1 = 0.0f;
        #pragma unroll
        for (int nf = 0; nf < 8; nf++) {
            sacc[nf][0] = __expf(sacc[nf][0] - m0);
            sacc[nf][1] = __expf(sacc[nf][1] - m0);
            sacc[nf][2] = __expf(sacc[nf][2] - m1);
            sacc[nf][3] = __expf(sacc[nf][3] - m1);
            ts0 += sacc[nf][0] + sacc[nf][1];
            ts1 += sacc[nf][2] + sacc[nf][3];
        }
        ts0 += __shfl_xor_sync(0xffffffffu, ts0, 1);
        ts0 += __shfl_xor_sync(0xffffffffu, ts0, 2);
        ts1 += __shfl_xor_sync(0xffffffffu, ts1, 1);
        ts1 += __shfl_xor_sync(0xffffffffu, ts1, 2);
        l0 = l0 * cor0 + ts0;
        l1 = l1 * cor1 + ts1;

        // ---- P C-frags -> A-frags in registers ----
        uint32_t pf[4][4];
        #pragma unroll
        for (int j = 0; j < 4; j++) {
            pf[j][0] = pack_h2(sacc[2 * j][0], sacc[2 * j][1]);
            pf[j][1] = pack_h2(sacc[2 * j][2], sacc[2 * j][3]);
            pf[j][2] = pack_h2(sacc[2 * j + 1][0], sacc[2 * j + 1][1]);
            pf[j][3] = pack_h2(sacc[2 * j + 1][2], sacc[2 * j + 1][3]);
        }

        #pragma unroll
        for (int df = 0; df < 16; df++) {
            oacc[df][0] *= cor0; oacc[df][1] *= cor0;
            oacc[df][2] *= cor1; oacc[df][3] *= cor1;
        }

        // ---- O += P @ V (V B-frags via ldmatrix.trans) ----
        #pragma unroll
        for (int j = 0; j < 4; j++) {
            #pragma unroll
            for (int dfp = 0; dfp < 8; dfp++) {
                int kvr = 16 * j + ((grp & 1) ? 8 : 0) + lr;
                int dc = dfp * 16 + ((grp & 2) ? 8 : 0);
                uint32_t b0, b1, b2, b3;
                ldsm_x4_t(b0, b1, b2, b3, svb + (kvr * FPITCH_H + dc) * 2);
                uint32_t bA[2] = {b0, b1}, bB[2] = {b2, b3};
                mma_f16(oacc[2 * dfp], pf[j], bA, oacc[2 * dfp]);
                mma_f16(oacc[2 * dfp + 1], pf[j], bB, oacc[2 * dfp + 1]);
            }
        }
    }

    // ---- epilogue: O /= l, write half ----
    const float inv0 = 1.0f / l0;
    const float inv1 = 1.0f / l1;
    #pragma unroll
    for (int df = 0; df < 16; df++) {
        const int gc = head * DH + df * 8 + 2 * r;
        *reinterpret_cast<__half2*>(O + (long long)(qbase + row0) * CC + gc) =
            __floats2half2_rn(oacc[df][0] * inv0, oacc[df][1] * inv0);
        *reinterpret_cast<__half2*>(O + (long long)(qbase + row0 + 8) * CC + gc) =
            __floats2half2_rn(oacc[df][2] * inv1, oacc[df][3] * inv1);
    }
}

// ---------------------------------------------------------------------------
// Block reduction
// ---------------------------------------------------------------------------
__device__ __forceinline__ float blockReduceSum(float v, float* red) {
    #pragma unroll
    for (int o = 16; o > 0; o >>= 1) v += __shfl_xor_sync(0xffffffffu, v, o);
    int w = threadIdx.x >> 5;
    if ((threadIdx.x & 31) == 0) red[w] = v;
    __syncthreads();
    float rr;
    if (threadIdx.x < 32) {
        rr = (threadIdx.x < (blockDim.x >> 5)) ? red[threadIdx.x] : 0.0f;
        #pragma unroll
        for (int o = 16; o > 0; o >>= 1) rr += __shfl_xor_sync(0xffffffffu, rr, o);
        if (threadIdx.x == 0) red[0] = rr;
    }
    __syncthreads();
    rr = red[0];
    __syncthreads();
    return rr;
}

// ---------------------------------------------------------------------------
// LN(a+b)*g+beta -> fp32 out + half out
// ---------------------------------------------------------------------------
__global__ void add_ln_kernel(const float* __restrict__ a, const float* __restrict__ b,
                              const float* __restrict__ g, const float* __restrict__ be,
                              float* __restrict__ out, __half* __restrict__ outH)
{
    long long row = blockIdx.x;
    const float* ar = a + row * CC;
    const float* br = b + row * CC;
    int tid = threadIdx.x;
    float x0 = ar[tid] + br[tid];
    float x1 = ar[tid + 256] + br[tid + 256];
    __shared__ float red[8];
    float mu = blockReduceSum(x0 + x1, red) * (1.0f / CC);
    float d0 = x0 - mu, d1 = x1 - mu;
    float var = blockReduceSum(d0 * d0 + d1 * d1, red) * (1.0f / CC);
    float rstd = rsqrtf(var + 1e-5f);
    float y0 = d0 * rstd * g[tid] + be[tid];
    float y1 = d1 * rstd * g[tid + 256] + be[tid + 256];
    out[row * CC + tid] = y0;
    out[row * CC + tid + 256] = y1;
    outH[row * CC + tid] = __float2half(y0);
    outH[row * CC + tid + 256] = __float2half(y1);
}

// ---------------------------------------------------------------------------
// Masked-mean aggregation -> half out (+ optional coef)
// ---------------------------------------------------------------------------
__global__ void agg_kernel(const float* __restrict__ X, int C,
                           const int* __restrict__ nbm,
                           const float* __restrict__ childMask,
                           __half* __restrict__ out, float* __restrict__ coefOut, int P)
{
    long long idx = (long long)blockIdx.x * blockDim.x + threadIdx.x;
    if (idx >= (long long)P * C) return;
    int p = (int)(idx / C);
    int c = (int)(idx % C);
    float sum = 0.0f, den = 0.0f, wsum = 0.0f;
    #pragma unroll
    for (int f = 0; f < FAN; f++) {
        float nb = (float)nbm[p * FAN + f];
        den += nb;
        float w = nb * (childMask ? childMask[p * FAN + f] : 1.0f);
        wsum += w;
        sum += w * X[(long long)(p * FAN + f) * C + c];
    }
    den = fmaxf(den, 1.0f);
    out[(long long)p * C + c] = __float2half(sum / den);
    if (coefOut && c == 0) coefOut[p] = wsum / den;
}

// ---------------------------------------------------------------------------
// fp32 -> fp16 elementwise
// ---------------------------------------------------------------------------
__global__ void cvt_kernel(const float* __restrict__ in, __half* __restrict__ out, int n)
{
    for (int i = blockIdx.x * blockDim.x + threadIdx.x; i < n; i += gridDim.x * blockDim.x)
        out[i] = __float2half(in[i]);
}

// ---------------------------------------------------------------------------
// Host orchestration
// ---------------------------------------------------------------------------
static void gemm(int M, int N, int K,
                 const __half* A, int lda, const __half* A2, int kSplit,
                 const __half* B, int ldb,
                 float* C, __half* Ch, int ldc,
                 const float* bias, const float* biasScale, int relu,
                 const float* addC, const float* rowMask)
{
    dim3 grid((N + GBN - 1) / GBN, (M + GBM - 1) / GBM);
    gemm_f16_kernel<<<grid, 256, GEMM_SMEM>>>(
        M, N, K, A, lda, A2, kSplit, B, ldb, C, Ch, ldc,
        bias, biasScale, relu, addC, rowMask);
}

static void cvt(const float* src, __half* dst, int n) {
    int blocks = (n + 255) / 256;
    if (blocks > 1024) blocks = 1024;
    cvt_kernel<<<blocks, 256>>>(src, dst, n);
}

struct Scratch {
    float *S1E, *S1N, *S0, *AGGC, *HL, *H1, *ATT, *H2;
    __half *S1Eh, *S0h, *AGGFh, *AGGh, *H1h, *QKVh, *ATTOh, *H2h, *FF1h;
    __half *embWh, *sageWh, *qkvWh, *outWh, *ffnW1h, *ffnW2h, *clsWh, *feats0h, *feats1h;
};

static Scratch get_scratch() {
    Scratch s; void* p;
    cudaGetSymbolAddress(&p, g_S1E);    s.S1E    = (float*)p;
    cudaGetSymbolAddress(&p, g_S1N);    s.S1N    = (float*)p;
    cudaGetSymbolAddress(&p, g_S0);     s.S0     = (float*)p;
    cudaGetSymbolAddress(&p, g_AGGC);   s.AGGC   = (float*)p;
    cudaGetSymbolAddress(&p, g_HL);     s.HL     = (float*)p;
    cudaGetSymbolAddress(&p, g_H1);     s.H1     = (float*)p;
    cudaGetSymbolAddress(&p, g_ATT);    s.ATT    = (float*)p;
    cudaGetSymbolAddress(&p, g_H2);     s.H2     = (float*)p;
    cudaGetSymbolAddress(&p, g_S1Eh);   s.S1Eh   = (__half*)p;
    cudaGetSymbolAddress(&p, g_S0h);    s.S0h    = (__half*)p;
    cudaGetSymbolAddress(&p, g_AGGFh);  s.AGGFh  = (__half*)p;
    cudaGetSymbolAddress(&p, g_AGGh);   s.AGGh   = (__half*)p;
    cudaGetSymbolAddress(&p, g_H1h);    s.H1h    = (__half*)p;
    cudaGetSymbolAddress(&p, g_QKVh);   s.QKVh   = (__half*)p;
    cudaGetSymbolAddress(&p, g_ATTOh);  s.ATTOh  = (__half*)p;
    cudaGetSymbolAddress(&p, g_H2h);    s.H2h    = (__half*)p;
    cudaGetSymbolAddress(&p, g_FF1h);   s.FF1h   = (__half*)p;
    cudaGetSymbolAddress(&p, g_embWh);  s.embWh  = (__half*)p;
    cudaGetSymbolAddress(&p, g_sageWh); s.sageWh = (__half*)p;
    cudaGetSymbolAddress(&p, g_qkvWh);  s.qkvWh  = (__half*)p;
    cudaGetSymbolAddress(&p, g_outWh);  s.outWh  = (__half*)p;
    cudaGetSymbolAddress(&p, g_ffnW1h); s.ffnW1h = (__half*)p;
    cudaGetSymbolAddress(&p, g_ffnW2h); s.ffnW2h = (__half*)p;
    cudaGetSymbolAddress(&p, g_clsWh);  s.clsWh  = (__half*)p;
    cudaGetSymbolAddress(&p, g_feats0h); s.feats0h = (__half*)p;
    cudaGetSymbolAddress(&p, g_feats1h); s.feats1h = (__half*)p;
    return s;
}

struct LayerW {
    const __half *sageW, *qkvW, *outW, *ffnW1, *ffnW2;
    const float *sageB, *qkvB, *outB, *ffnB1, *ffnB2;
    const float *n1g, *n1b, *n2g, *n2b;
};

static void block_forward(int n, const float* sf, const __half* sfh, const __half* agg,
                          float* outState, __half* outStateH,
                          const float* rowMask, const LayerW& w, const Scratch& s)
{
    // GraphSAGE: [sfh | agg] @ sageW^T
    gemm(n, CC, 2 * CC, sfh, CC, agg, CC, w.sageW, 2 * CC,
         s.HL, nullptr, CC, w.sageB, nullptr, 0, nullptr, nullptr);
    add_ln_kernel<<<n, 256>>>(sf, s.HL, w.n1g, w.n1b, s.H1, s.H1h);

    gemm(n, 3 * CC, CC, s.H1h, CC, nullptr, CC, w.qkvW, CC,
         nullptr, s.QKVh, 3 * CC, w.qkvB, nullptr, 0, nullptr, nullptr);

    {
        dim3 grid(n / 64, HH);
        flash_f16_kernel<<<grid, 128>>>(s.QKVh, s.ATTOh, n);
    }

    gemm(n, CC, CC, s.ATTOh, CC, nullptr, CC, w.outW, CC,
         s.ATT, nullptr, CC, w.outB, nullptr, 0, nullptr, nullptr);
    add_ln_kernel<<<n, 256>>>(s.H1, s.ATT, w.n2g, w.n2b, s.H2, s.H2h);

    gemm(n, 2 * CC, CC, s.H2h, CC, nullptr, CC, w.ffnW1, CC,
         nullptr, s.FF1h, 2 * CC, w.ffnB1, nullptr, 1, nullptr, nullptr);
    gemm(n, CC, 2 * CC, s.FF1h, 2 * CC, nullptr, 2 * CC, w.ffnW2, 2 * CC,
         outState, outStateH, CC, w.ffnB2, nullptr, 0, s.H2, rowMask);
}

extern "C" void kernel_launch(void* const* d_in, const int* in_sizes, int n_in,
                              void* d_out, int out_size)
{
    const float* feats0  = (const float*)d_in[0];
    const float* feats1  = (const float*)d_in[1];
    const float* feats2  = (const float*)d_in[2];
    const float* nmask0  = (const float*)d_in[3];
    const float* nmask1  = (const float*)d_in[4];
    const float* nmask2  = (const float*)d_in[5];
    const int*   nbmask0 = (const int*)d_in[6];
    const int*   nbmask1 = (const int*)d_in[7];
    const float* emb_w   = (const float*)d_in[8];
    const float* emb_b   = (const float*)d_in[9];
    const float* sage_w  = (const float*)d_in[10];
    const float* sage_b  = (const float*)d_in[11];
    const float* qkv_w   = (const float*)d_in[12];
    const float* qkv_b   = (const float*)d_in[13];
    const float* out_w   = (const float*)d_in[14];
    const float* out_b   = (const float*)d_in[15];
    const float* n1_g    = (const float*)d_in[16];
    const float* n1_b    = (const float*)d_in[17];
    const float* n2_g    = (const float*)d_in[18];
    const float* n2_b    = (const float*)d_in[19];
    const float* ffn_w1  = (const float*)d_in[20];
    const float* ffn_b1  = (const float*)d_in[21];
    const float* ffn_w2  = (const float*)d_in[22];
    const float* ffn_b2  = (const float*)d_in[23];
    const float* cls_w   = (const float*)d_in[24];
    const float* cls_b   = (const float*)d_in[25];
    float* out = (float*)d_out;

    cudaFuncSetAttribute(gemm_f16_kernel, cudaFuncAttributeMaxDynamicSharedMemorySize, GEMM_SMEM);

    Scratch s = get_scratch();

    // ---- convert weights + input feats to half (deterministic each call) ----
    cvt(emb_w,  s.embWh,  CC * INDIM);
    cvt(sage_w, s.sageWh, NL * CC * 2 * CC);
    cvt(qkv_w,  s.qkvWh,  NL * 3 * CC * CC);
    cvt(out_w,  s.outWh,  NL * CC * CC);
    cvt(ffn_w1, s.ffnW1h, NL * 2 * CC * CC);
    cvt(ffn_w2, s.ffnW2h, NL * CC * 2 * CC);
    cvt(cls_w,  s.clsWh,  NC * CC);
    cvt(feats0, s.feats0h, N0 * INDIM);
    cvt(feats1, s.feats1h, N1 * INDIM);

    LayerW w[NL];
    for (int li = 0; li < NL; li++) {
        w[li].sageW = s.sageWh + (long long)li * CC * 2 * CC;
        w[li].qkvW  = s.qkvWh  + (long long)li * 3 * CC * CC;
        w[li].outW  = s.outWh  + (long long)li * CC * CC;
        w[li].ffnW1 = s.ffnW1h + (long long)li * 2 * CC * CC;
        w[li].ffnW2 = s.ffnW2h + (long long)li * CC * 2 * CC;
        w[li].sageB = sage_b + li * CC;
        w[li].qkvB  = qkv_b  + li * 3 * CC;
        w[li].outB  = out_b  + li * CC;
        w[li].ffnB1 = ffn_b1 + li * 2 * CC;
        w[li].ffnB2 = ffn_b2 + li * CC;
        w[li].n1g = n1_g + li * CC;  w[li].n1b = n1_b + li * CC;
        w[li].n2g = n2_g + li * CC;  w[li].n2b = n2_b + li * CC;
    }

    // ---- embeddings (depth 0, 1), masked; write fp32 + half ----
    gemm(N0, CC, INDIM, s.feats0h, INDIM, nullptr, INDIM, s.embWh, INDIM,
         s.S0, s.S0h, CC, emb_b, nullptr, 0, nullptr, nmask0);
    gemm(N1, CC, INDIM, s.feats1h, INDIM, nullptr, INDIM, s.embWh, INDIM,
         s.S1E, s.S1Eh, CC, emb_b, nullptr, 0, nullptr, nmask1);

    // ---- depth-2: aggregate RAW feats2 then one embedding GEMM ----
    agg_kernel<<<(int)(((long long)N1 * INDIM + 255) / 256), 256>>>(
        feats2, INDIM, nbmask1, nmask2, s.AGGFh, s.AGGC, N1);
    gemm(N1, CC, INDIM, s.AGGFh, INDIM, nullptr, INDIM, s.embWh, INDIM,
         nullptr, s.AGGh, CC, emb_b, s.AGGC, 0, nullptr, nullptr);

    // ---- layer 0, depth 1 (n=4096); S1N fp32 only (used for later agg) ----
    block_forward(N1, s.S1E, s.S1Eh, s.AGGh, s.S1N, nullptr, nmask1, w[0], s);

    // ---- layer 0, depth 0 ----
    agg_kernel<<<(int)(((long long)N0 * CC + 255) / 256), 256>>>(
        s.S1E, CC, nbmask0, nullptr, s.AGGh, nullptr, N0);
    block_forward(N0, s.S0, s.S0h, s.AGGh, s.S0, s.S0h, nmask0, w[0], s);

    // ---- layer 1, depth 0 ----
    agg_kernel<<<(int)(((long long)N0 * CC + 255) / 256), 256>>>(
        s.S1N, CC, nbmask0, nullptr, s.AGGh, nullptr, N0);
    block_forward(N0, s.S0, s.S0h, s.AGGh, s.S0, s.S0h, nmask0, w[1], s);

    // ---- classifier ----
    gemm(N0, NC, CC, s.S0h, CC, nullptr, CC, s.clsWh, CC,
         out, nullptr, NC, cls_b, nullptr, 0, nullptr, nullptr);
}